// round 4
// baseline (speedup 1.0000x reference)
#include <cuda_runtime.h>
#include <cstddef>

#define NN   50000      // nodes
#define NE   800000     // edges
#define DD   128        // feature dim (in/hidden)
#define KK   256        // concat dim = 2*DD

typedef unsigned long long ull;

// ---------------- packed f32x2 helpers ----------------
__device__ __forceinline__ ull pack2(float x, float y) {
    ull r; asm("mov.b64 %0, {%1, %2};" : "=l"(r) : "f"(x), "f"(y)); return r;
}
__device__ __forceinline__ float2 unpack2(ull v) {
    float2 r; asm("mov.b64 {%0, %1}, %2;" : "=f"(r.x), "=f"(r.y) : "l"(v)); return r;
}
__device__ __forceinline__ void fma2(ull& d, ull a, ull b) {
    asm("fma.rn.f32x2 %0, %1, %2, %0;" : "+l"(d) : "l"(a), "l"(b));
}

// ---------------- device scratch (static; no allocs allowed) ----------------
__device__ int   g_cnt[NN];
__device__ int   g_off[NN + 1];
__device__ int   g_col[NE];
__device__ float g_wgt[NE];
__device__ float g_deg[NN];
__device__ float g_agg[NN * DD];
__device__ float g_h0[NN * DD];
__device__ float g_h1[NN * DD];
__device__ float g_Wt0[KK * 128];  // W0^T : [256][128]
__device__ float g_Wt1[KK * 128];  // W1^T : [256][128]
__device__ float g_Wt2[KK * 64];   // W2^T : [256][64]

// ---------------- weight transpose: Wt[k][n] = W[n][k] ----------------
__global__ void transpose_W(const float* __restrict__ W0,
                            const float* __restrict__ W1,
                            const float* __restrict__ W2) {
    int i = blockIdx.x * 256 + threadIdx.x;
    if (i < KK * 128) {
        g_Wt0[i] = W0[(i % 128) * KK + i / 128];
    } else if (i < 2 * KK * 128) {
        int j = i - KK * 128;
        g_Wt1[j] = W1[(j % 128) * KK + j / 128];
    } else if (i < 2 * KK * 128 + KK * 64) {
        int j = i - 2 * KK * 128;
        g_Wt2[j] = W2[(j % 64) * KK + j / 64];
    }
}

// ---------------- CSR build ----------------
__global__ void count_kernel(const int* __restrict__ ei, const float* __restrict__ ew) {
    int e = blockIdx.x * blockDim.x + threadIdx.x;
    if (e >= NE) return;
    int r = ei[e];
    atomicAdd(&g_cnt[r], 1);
    atomicAdd(&g_deg[r], ew[e]);
}

// vectorized single-block scan: 1024 threads x 4 elems = 4096/round
__global__ void scan_kernel() {
    __shared__ int warp_sums[32];
    __shared__ int s_total;
    __shared__ int s_base;
    const int tid = threadIdx.x, lane = tid & 31, wid = tid >> 5;
    if (tid == 0) s_base = 0;
    __syncthreads();
    for (int start = 0; start < NN; start += 4096) {
        int i0 = start + tid * 4;
        int v[4];
        #pragma unroll
        for (int j = 0; j < 4; ++j) v[j] = (i0 + j < NN) ? g_cnt[i0 + j] : 0;
        int tsum = v[0] + v[1] + v[2] + v[3];
        int incl = tsum;
        #pragma unroll
        for (int o = 1; o < 32; o <<= 1) {
            int t = __shfl_up_sync(0xffffffffu, incl, o);
            if (lane >= o) incl += t;
        }
        if (lane == 31) warp_sums[wid] = incl;
        __syncthreads();
        if (wid == 0) {
            int wv = warp_sums[lane];
            int ws = wv;
            #pragma unroll
            for (int o = 1; o < 32; o <<= 1) {
                int t = __shfl_up_sync(0xffffffffu, ws, o);
                if (lane >= o) ws += t;
            }
            if (lane == 31) s_total = ws;
            warp_sums[lane] = ws - wv;
        }
        __syncthreads();
        int run = s_base + incl - tsum + warp_sums[wid];
        #pragma unroll
        for (int j = 0; j < 4; ++j) {
            if (i0 + j < NN) { g_off[i0 + j] = run; g_cnt[i0 + j] = run; run += v[j]; }
        }
        __syncthreads();
        if (tid == 0) s_base += s_total;
        __syncthreads();
    }
    if (tid == 0) g_off[NN] = s_base;
}

__global__ void fill_kernel(const int* __restrict__ ei, const float* __restrict__ ew) {
    int e = blockIdx.x * blockDim.x + threadIdx.x;
    if (e >= NE) return;
    int r = ei[e];
    int c = ei[NE + e];
    float w = ew[e];
    int pos = atomicAdd(&g_cnt[r], 1);
    g_col[pos] = c;
    g_wgt[pos] = w;
}

// ---------------- aggregation: warp per node, CSR gather ----------------
__global__ void agg_kernel(const float* __restrict__ xin) {
    int gw = (blockIdx.x * blockDim.x + threadIdx.x) >> 5;
    if (gw >= NN) return;
    const int lane = threadIdx.x & 31;
    const int s = g_off[gw];
    const int e = g_off[gw + 1];
    float4 acc = make_float4(0.f, 0.f, 0.f, 0.f);
    for (int base = s; base < e; base += 32) {
        int nn = min(32, e - base);
        int c = 0; float w = 0.f;
        if (lane < nn) { c = g_col[base + lane]; w = g_wgt[base + lane]; }
        for (int j = 0; j < nn; ++j) {
            int cj = __shfl_sync(0xffffffffu, c, j);
            float wj = __shfl_sync(0xffffffffu, w, j);
            float4 v = *(const float4*)(xin + (size_t)cj * DD + lane * 4);
            acc.x = fmaf(v.x, wj, acc.x);
            acc.y = fmaf(v.y, wj, acc.y);
            acc.z = fmaf(v.z, wj, acc.z);
            acc.w = fmaf(v.w, wj, acc.w);
        }
    }
    float invd = 1.0f / fmaxf(g_deg[gw], 1.0f);
    float4* o = (float4*)(g_agg + (size_t)gw * DD);
    o[lane] = make_float4(acc.x * invd, acc.y * invd, acc.z * invd, acc.w * invd);
}

// ---------------- fused GEMM (double-buffered, duplicated-A smem) ------------
// out = [xin | agg] @ W^T + b (+relu). BM=128, BK=16, K=256.
// As2 holds each A value DUPLICATED as an f32x2 pair -> compute loop loads
// operands directly as packed 64-bit pairs (no MOV packing on the fma path).
template <int BN, int TN, bool RELU>
__global__ void __launch_bounds__(256, 2) gemm_kernel(
    const float* __restrict__ xin,
    const float* __restrict__ Wt,    // [256][BN]
    const float* __restrict__ bias,  // [BN]
    float* __restrict__ out)         // [NN, BN]
{
    __shared__ __align__(16) float As2[2][16][256];   // duplicated pairs
    __shared__ __align__(16) float Bs[2][16][BN];

    constexpr int G   = TN / 2;                 // 4 or 2 floats per group
    constexpr int NP  = G / 2;                  // 2 or 1 f32x2 pairs per group
    constexpr int BLD = (BN * 16) / (4 * 256);  // B float4 per thread (2 or 1)

    const int tid = threadIdx.x;
    const int tx = tid & 15;
    const int ty = tid >> 4;
    const int m0 = blockIdx.x * 128;

    ull acc[8][2][NP];
    #pragma unroll
    for (int i = 0; i < 8; ++i)
        #pragma unroll
        for (int g = 0; g < 2; ++g)
            #pragma unroll
            for (int p = 0; p < NP; ++p) acc[i][g][p] = 0ULL;

    float4 stA[2], stB[BLD];

    auto loadT = [&](int kt) {
        const int kg = kt * 16;
        const float* Asrc = (kt < 8) ? (xin + kg) : (g_agg + (kg - 128));
        #pragma unroll
        for (int it = 0; it < 2; ++it) {
            int idx = tid * 2 + it;          // 0..511 float4 slots (128 rows x 4)
            int row = idx >> 2;
            int gr = m0 + row;
            stA[it] = make_float4(0.f, 0.f, 0.f, 0.f);
            if (gr < NN) stA[it] = *(const float4*)(Asrc + (size_t)gr * DD + (idx & 3) * 4);
        }
        #pragma unroll
        for (int it = 0; it < BLD; ++it) {
            int idx = tid + it * 256;
            stB[it] = *(const float4*)(Wt + (size_t)kg * BN + idx * 4);
        }
    };
    auto storeT = [&](int buf) {
        #pragma unroll
        for (int it = 0; it < 2; ++it) {
            int idx = tid * 2 + it;
            int row = idx >> 2;
            int cf = idx & 3;
            float v[4] = {stA[it].x, stA[it].y, stA[it].z, stA[it].w};
            #pragma unroll
            for (int j = 0; j < 4; ++j)
                *(ull*)&As2[buf][cf * 4 + j][2 * row] = pack2(v[j], v[j]);
        }
        #pragma unroll
        for (int it = 0; it < BLD; ++it) {
            int idx = tid + it * 256;
            *(float4*)(&Bs[buf][0][0] + idx * 4) = stB[it];
        }
    };

    loadT(0);
    storeT(0);
    __syncthreads();

    #pragma unroll 1
    for (int kt = 0; kt < 16; ++kt) {
        const int buf = kt & 1;
        if (kt < 15) loadT(kt + 1);
        #pragma unroll
        for (int k = 0; k < 16; ++k) {
            // a-pairs: 8 duplicated f32x2, 4x LDS.128, already packed
            ull a2[8];
            const ulonglong2* ap = (const ulonglong2*)&As2[buf][k][ty * 16];
            #pragma unroll
            for (int q = 0; q < 4; ++q) {
                ulonglong2 t = ap[q];
                a2[q * 2]     = t.x;
                a2[q * 2 + 1] = t.y;
            }
            // b-pairs: direct packed loads
            ull b2[2][NP];
            #pragma unroll
            for (int g = 0; g < 2; ++g) {
                if (NP == 2) {
                    ulonglong2 t = *(const ulonglong2*)&Bs[buf][k][g * (BN / 2) + tx * G];
                    b2[g][0] = t.x;
                    if (NP > 1) b2[g][NP - 1] = t.y;
                } else {
                    b2[g][0] = *(const ull*)&Bs[buf][k][g * (BN / 2) + tx * G];
                }
            }
            #pragma unroll
            for (int i = 0; i < 8; ++i)
                #pragma unroll
                for (int g = 0; g < 2; ++g)
                    #pragma unroll
                    for (int p = 0; p < NP; ++p)
                        fma2(acc[i][g][p], a2[i], b2[g][p]);
        }
        if (kt < 15) {
            storeT(buf ^ 1);
            __syncthreads();
        }
    }

    // bias
    float2 bv[2][NP];
    #pragma unroll
    for (int g = 0; g < 2; ++g)
        #pragma unroll
        for (int p = 0; p < NP; ++p) {
            int c = g * (BN / 2) + tx * G + p * 2;
            bv[g][p] = make_float2(__ldg(&bias[c]), __ldg(&bias[c + 1]));
        }

    #pragma unroll
    for (int i = 0; i < 8; ++i) {
        int r = m0 + ty * 8 + i;
        if (r < NN) {
            #pragma unroll
            for (int g = 0; g < 2; ++g) {
                float vals[G];
                #pragma unroll
                for (int p = 0; p < NP; ++p) {
                    float2 t = unpack2(acc[i][g][p]);
                    float v0 = t.x + bv[g][p].x;
                    float v1 = t.y + bv[g][p].y;
                    if (RELU) { v0 = fmaxf(v0, 0.f); v1 = fmaxf(v1, 0.f); }
                    vals[p * 2] = v0; vals[p * 2 + 1] = v1;
                }
                float* op = out + (size_t)r * BN + g * (BN / 2) + tx * G;
                if (G == 4) {
                    *(float4*)op = make_float4(vals[0], vals[1], vals[2 % G], vals[3 % G]);
                } else {
                    *(float2*)op = make_float2(vals[0], vals[1]);
                }
            }
        }
    }
}

// ---------------- launch ----------------
extern "C" void kernel_launch(void* const* d_in, const int* in_sizes, int n_in,
                              void* d_out, int out_size) {
    (void)in_sizes; (void)n_in; (void)out_size;
    const float* x  = (const float*)d_in[0];
    const int*   ei = (const int*)d_in[1];
    const float* ew = (const float*)d_in[2];
    const float* W0 = (const float*)d_in[3];
    const float* b0 = (const float*)d_in[4];
    const float* W1 = (const float*)d_in[5];
    const float* b1 = (const float*)d_in[6];
    const float* W2 = (const float*)d_in[7];
    const float* b2 = (const float*)d_in[8];
    float* out = (float*)d_out;

    void *p_cnt, *p_deg, *p_h0, *p_h1, *p_w0, *p_w1, *p_w2;
    cudaGetSymbolAddress(&p_cnt, g_cnt);
    cudaGetSymbolAddress(&p_deg, g_deg);
    cudaGetSymbolAddress(&p_h0,  g_h0);
    cudaGetSymbolAddress(&p_h1,  g_h1);
    cudaGetSymbolAddress(&p_w0,  g_Wt0);
    cudaGetSymbolAddress(&p_w1,  g_Wt1);
    cudaGetSymbolAddress(&p_w2,  g_Wt2);
    float* h0 = (float*)p_h0;
    float* h1 = (float*)p_h1;

    cudaMemsetAsync(p_cnt, 0, NN * sizeof(int), 0);
    cudaMemsetAsync(p_deg, 0, NN * sizeof(float), 0);

    const int totW = 2 * KK * 128 + KK * 64;
    transpose_W<<<(totW + 255) / 256, 256>>>(W0, W1, W2);
    count_kernel<<<(NE + 255) / 256, 256>>>(ei, ew);
    scan_kernel<<<1, 1024>>>();
    fill_kernel<<<(NE + 255) / 256, 256>>>(ei, ew);

    const int aggBlocks  = (NN + 7) / 8;
    const int gemmBlocks = (NN + 127) / 128;

    agg_kernel<<<aggBlocks, 256>>>(x);
    gemm_kernel<128, 8, true><<<gemmBlocks, 256>>>(x, (const float*)p_w0, b0, h0);

    agg_kernel<<<aggBlocks, 256>>>(h0);
    gemm_kernel<128, 8, true><<<gemmBlocks, 256>>>(h0, (const float*)p_w1, b1, h1);

    agg_kernel<<<aggBlocks, 256>>>(h1);
    gemm_kernel<64, 4, false><<<gemmBlocks, 256>>>(h1, (const float*)p_w2, b2, out);
}

// round 6
// speedup vs baseline: 1.4276x; 1.4276x over previous
#include <cuda_runtime.h>
#include <cuda_bf16.h>
#include <cstdint>
#include <cstddef>

#define NN   50000
#define NE   800000
#define DD   128
#define KK   256

// ================= low-level helpers =================
__device__ __forceinline__ uint32_t smem_u32(const void* p) {
    uint32_t a;
    asm("{ .reg .u64 t; cvta.to.shared.u64 t, %1; cvt.u32.u64 %0, t; }" : "=r"(a) : "l"(p));
    return a;
}
__device__ __forceinline__ void ldsm4(uint32_t* r, uint32_t addr) {
    asm volatile("ldmatrix.sync.aligned.m8n8.x4.shared.b16 {%0,%1,%2,%3}, [%4];"
                 : "=r"(r[0]), "=r"(r[1]), "=r"(r[2]), "=r"(r[3]) : "r"(addr));
}
__device__ __forceinline__ void mma16816(float* d, const uint32_t* a, uint32_t b0, uint32_t b1) {
    asm volatile(
        "mma.sync.aligned.m16n8k16.row.col.f32.bf16.bf16.f32 "
        "{%0,%1,%2,%3}, {%4,%5,%6,%7}, {%8,%9}, {%0,%1,%2,%3};"
        : "+f"(d[0]), "+f"(d[1]), "+f"(d[2]), "+f"(d[3])
        : "r"(a[0]), "r"(a[1]), "r"(a[2]), "r"(a[3]), "r"(b0), "r"(b1));
}
__device__ __forceinline__ void cpa16(uint32_t dst, const void* src, int sz) {
    asm volatile("cp.async.cg.shared.global [%0], [%1], 16, %2;"
                 :: "r"(dst), "l"(src), "r"(sz));
}
#define CPA_COMMIT() asm volatile("cp.async.commit_group;" ::: "memory")

// ================= device scratch =================
__device__ int   g_cnt[NN];
__device__ int   g_off[NN + 1];
__device__ int   g_col[NE];
__device__ float g_wgt[NE];
__device__ float g_deg[NN];
__device__ float g_h[NN * DD];                       // fp32 hidden (for agg gather)
__device__ __nv_bfloat16 g_xhA[NN * DD], g_xlA[NN * DD];   // layer input split (ping)
__device__ __nv_bfloat16 g_xhB[NN * DD], g_xlB[NN * DD];   // (pong)
__device__ __nv_bfloat16 g_ah[NN * DD],  g_al[NN * DD];    // agg split
__device__ __nv_bfloat16 g_Wh0[128 * KK], g_Wl0[128 * KK];
__device__ __nv_bfloat16 g_Wh1[128 * KK], g_Wl1[128 * KK];
__device__ __nv_bfloat16 g_Wh2[64 * KK],  g_Wl2[64 * KK];

// ================= weight split (plain [n][k] layout) =================
__global__ void prep_W(const float* __restrict__ W0,
                       const float* __restrict__ W1,
                       const float* __restrict__ W2) {
    int i = blockIdx.x * 256 + threadIdx.x;
    const int L = 128 * KK;
    float w; __nv_bfloat16 *dh, *dl; int j;
    if (i < L)               { j = i;         w = W0[j]; dh = g_Wh0; dl = g_Wl0; }
    else if (i < 2 * L)      { j = i - L;     w = W1[j]; dh = g_Wh1; dl = g_Wl1; }
    else if (i < 2 * L + 64 * KK) { j = i - 2 * L; w = W2[j]; dh = g_Wh2; dl = g_Wl2; }
    else return;
    __nv_bfloat16 hi = __float2bfloat16(w);
    __nv_bfloat16 lo = __float2bfloat16(w - __bfloat162float(hi));
    dh[j] = hi;
    dl[j] = lo;
}

// ================= split x (once) =================
__global__ void split_x(const float* __restrict__ x) {
    int i = blockIdx.x * 256 + threadIdx.x;         // float4 index
    if (i >= NN * DD / 4) return;
    float4 v = ((const float4*)x)[i];
    __nv_bfloat162 h0 = __floats2bfloat162_rn(v.x, v.y);
    __nv_bfloat162 h1 = __floats2bfloat162_rn(v.z, v.w);
    __nv_bfloat162 l0 = __floats2bfloat162_rn(v.x - __bfloat162float(h0.x),
                                              v.y - __bfloat162float(h0.y));
    __nv_bfloat162 l1 = __floats2bfloat162_rn(v.z - __bfloat162float(h1.x),
                                              v.w - __bfloat162float(h1.y));
    ((__nv_bfloat162*)g_xhA)[i * 2]     = h0;
    ((__nv_bfloat162*)g_xhA)[i * 2 + 1] = h1;
    ((__nv_bfloat162*)g_xlA)[i * 2]     = l0;
    ((__nv_bfloat162*)g_xlA)[i * 2 + 1] = l1;
}

// ================= CSR build =================
__global__ void count_kernel(const int* __restrict__ ei, const float* __restrict__ ew) {
    int e = blockIdx.x * blockDim.x + threadIdx.x;
    if (e >= NE) return;
    int r = ei[e];
    atomicAdd(&g_cnt[r], 1);
    atomicAdd(&g_deg[r], ew[e]);
}

__global__ void scan_kernel() {
    __shared__ int warp_sums[32];
    __shared__ int s_total;
    __shared__ int s_base;
    const int tid = threadIdx.x, lane = tid & 31, wid = tid >> 5;
    if (tid == 0) s_base = 0;
    __syncthreads();
    for (int start = 0; start < NN; start += 4096) {
        int i0 = start + tid * 4;
        int v[4];
        #pragma unroll
        for (int j = 0; j < 4; ++j) v[j] = (i0 + j < NN) ? g_cnt[i0 + j] : 0;
        int tsum = v[0] + v[1] + v[2] + v[3];
        int incl = tsum;
        #pragma unroll
        for (int o = 1; o < 32; o <<= 1) {
            int t = __shfl_up_sync(0xffffffffu, incl, o);
            if (lane >= o) incl += t;
        }
        if (lane == 31) warp_sums[wid] = incl;
        __syncthreads();
        if (wid == 0) {
            int wv = warp_sums[lane];
            int ws = wv;
            #pragma unroll
            for (int o = 1; o < 32; o <<= 1) {
                int t = __shfl_up_sync(0xffffffffu, ws, o);
                if (lane >= o) ws += t;
            }
            if (lane == 31) s_total = ws;
            warp_sums[lane] = ws - wv;
        }
        __syncthreads();
        int run = s_base + incl - tsum + warp_sums[wid];
        #pragma unroll
        for (int j = 0; j < 4; ++j) {
            if (i0 + j < NN) { g_off[i0 + j] = run; g_cnt[i0 + j] = run; run += v[j]; }
        }
        __syncthreads();
        if (tid == 0) s_base += s_total;
        __syncthreads();
    }
    if (tid == 0) g_off[NN] = s_base;
}

__global__ void fill_kernel(const int* __restrict__ ei, const float* __restrict__ ew) {
    int e = blockIdx.x * blockDim.x + threadIdx.x;
    if (e >= NE) return;
    int r = ei[e];
    int c = ei[NE + e];
    float w = ew[e];
    int pos = atomicAdd(&g_cnt[r], 1);
    g_col[pos] = c;
    g_wgt[pos] = w;
}

// ================= aggregation: warp per node, writes bf16 split =================
__global__ void agg_kernel(const float* __restrict__ xin) {
    int gw = (blockIdx.x * blockDim.x + threadIdx.x) >> 5;
    if (gw >= NN) return;
    const int lane = threadIdx.x & 31;
    const int s = g_off[gw];
    const int e = g_off[gw + 1];
    float4 acc = make_float4(0.f, 0.f, 0.f, 0.f);
    for (int base = s; base < e; base += 32) {
        int nn = min(32, e - base);
        int c = 0; float w = 0.f;
        if (lane < nn) { c = g_col[base + lane]; w = g_wgt[base + lane]; }
        for (int j = 0; j < nn; ++j) {
            int cj = __shfl_sync(0xffffffffu, c, j);
            float wj = __shfl_sync(0xffffffffu, w, j);
            float4 v = *(const float4*)(xin + (size_t)cj * DD + lane * 4);
            acc.x = fmaf(v.x, wj, acc.x);
            acc.y = fmaf(v.y, wj, acc.y);
            acc.z = fmaf(v.z, wj, acc.z);
            acc.w = fmaf(v.w, wj, acc.w);
        }
    }
    float invd = 1.0f / fmaxf(g_deg[gw], 1.0f);
    float v0 = acc.x * invd, v1 = acc.y * invd, v2 = acc.z * invd, v3 = acc.w * invd;
    __nv_bfloat162 h01 = __floats2bfloat162_rn(v0, v1);
    __nv_bfloat162 h23 = __floats2bfloat162_rn(v2, v3);
    __nv_bfloat162 l01 = __floats2bfloat162_rn(v0 - __bfloat162float(h01.x),
                                               v1 - __bfloat162float(h01.y));
    __nv_bfloat162 l23 = __floats2bfloat162_rn(v2 - __bfloat162float(h23.x),
                                               v3 - __bfloat162float(h23.y));
    __nv_bfloat162* oh = (__nv_bfloat162*)g_ah + (size_t)gw * 64 + lane * 2;
    __nv_bfloat162* ol = (__nv_bfloat162*)g_al + (size_t)gw * 64 + lane * 2;
    oh[0] = h01; oh[1] = h23;
    ol[0] = l01; ol[1] = l23;
}

// ================= HMMA GEMM: out = [X|Agg] @ W^T + b =================
// BM=128, BK=64 (4 tiles over K=256), 8 warps (2m x 4n), warp tile 64 x (BN/4).
// 3-term bf16 split: D = Ah*Wh + Ah*Wl + Al*Wh, fp32 accum.
template <int BN, bool RELU, bool SPLIT>
__global__ void __launch_bounds__(256, 1) tgemm_kernel(
    const __nv_bfloat16* __restrict__ Xh, const __nv_bfloat16* __restrict__ Xl,
    const __nv_bfloat16* __restrict__ Wh, const __nv_bfloat16* __restrict__ Wl,
    const float* __restrict__ bias,
    float* __restrict__ outF,
    __nv_bfloat16* __restrict__ outHh, __nv_bfloat16* __restrict__ outHl)
{
    extern __shared__ __align__(16) char smem[];
    constexpr int PADB  = 144;                 // bytes per 64-col bf16 row (+16B pad)
    constexpr int ASZ   = 128 * PADB;          // 18432 B
    constexpr int BSZ   = BN * PADB;
    constexpr int STAGE = 2 * ASZ + 2 * BSZ;
    constexpr int WARP_N = BN / 4;             // 32 or 16
    constexpr int NFRAG  = WARP_N / 8;         // 4 or 2
    constexpr int NLB    = NFRAG / 2;          // 2 or 1
    constexpr int BLOADS = (BN * 8) / 256;     // B 16B-chunks per thread (4 or 2)

    const int tid  = threadIdx.x;
    const int lane = tid & 31;
    const int wid  = tid >> 5;
    const int wm   = wid >> 2;                 // 0..1
    const int wn   = wid & 3;                  // 0..3
    const int m0   = blockIdx.x * 128;

    const uint32_t sbase = smem_u32(smem);

    // per-thread ldmatrix offsets (bytes, within a buffer)
    const uint32_t offA = (uint32_t)((wm * 64 + (lane & 15)) * PADB + (lane >> 4) * 16);
    const uint32_t offB = (uint32_t)((wn * WARP_N + (lane & 7) + ((lane >> 4) << 3)) * PADB
                                     + (lane & 8) * 2);

    float acc[4][NFRAG][4];
    #pragma unroll
    for (int i = 0; i < 4; ++i)
        #pragma unroll
        for (int j = 0; j < NFRAG; ++j)
            #pragma unroll
            for (int q = 0; q < 4; ++q) acc[i][j][q] = 0.f;

    auto issue = [&](int t, int b) {
        const uint32_t st = sbase + b * STAGE;
        const __nv_bfloat16* axh = (t < 2) ? Xh : g_ah;
        const __nv_bfloat16* axl = (t < 2) ? Xl : g_al;
        const int colb = (t & 1) * 64;
        #pragma unroll
        for (int i = 0; i < 4; ++i) {
            int idx = tid + i * 256;            // 0..1023: 128 rows x 8 chunks
            int row = idx >> 3, ch = idx & 7;
            int gr = m0 + row;
            int ok = (gr < NN) ? 16 : 0;
            int grc = (gr < NN) ? gr : 0;
            size_t go = (size_t)grc * DD + colb + ch * 8;
            uint32_t sa = (uint32_t)(row * PADB + ch * 16);
            cpa16(st + sa,        axh + go, ok);
            cpa16(st + ASZ + sa,  axl + go, ok);
        }
        #pragma unroll
        for (int i = 0; i < BLOADS; ++i) {
            int idx = tid + i * 256;            // BN rows x 8 chunks
            int row = idx >> 3, ch = idx & 7;
            size_t go = (size_t)row * KK + t * 64 + ch * 8;
            uint32_t sa = (uint32_t)(row * PADB + ch * 16);
            cpa16(st + 2 * ASZ + sa,       Wh + go, 16);
            cpa16(st + 2 * ASZ + BSZ + sa, Wl + go, 16);
        }
        CPA_COMMIT();
    };

    auto compute = [&](int b) {
        const uint32_t st  = sbase + b * STAGE;
        const uint32_t pAh = st + offA;
        const uint32_t pAl = st + ASZ + offA;
        const uint32_t pBh = st + 2 * ASZ + offB;
        const uint32_t pBl = st + 2 * ASZ + BSZ + offB;
        #pragma unroll
        for (int kk = 0; kk < 4; ++kk) {
            const int kb = kk * 32;             // 16 bf16 = 32 bytes
            uint32_t a[4][4];
            #pragma unroll
            for (int mi = 0; mi < 4; ++mi) ldsm4(a[mi], pAh + mi * (16 * PADB) + kb);
            uint32_t bh[NLB][4];
            #pragma unroll
            for (int p = 0; p < NLB; ++p) ldsm4(bh[p], pBh + p * (16 * PADB) + kb);
            #pragma unroll
            for (int mi = 0; mi < 4; ++mi)
                #pragma unroll
                for (int p = 0; p < NLB; ++p) {
                    mma16816(acc[mi][p * 2],     a[mi], bh[p][0], bh[p][1]);
                    mma16816(acc[mi][p * 2 + 1], a[mi], bh[p][2], bh[p][3]);
                }
            uint32_t bl[NLB][4];
            #pragma unroll
            for (int p = 0; p < NLB; ++p) ldsm4(bl[p], pBl + p * (16 * PADB) + kb);
            #pragma unroll
            for (int mi = 0; mi < 4; ++mi)
                #pragma unroll
                for (int p = 0; p < NLB; ++p) {
                    mma16816(acc[mi][p * 2],     a[mi], bl[p][0], bl[p][1]);
                    mma16816(acc[mi][p * 2 + 1], a[mi], bl[p][2], bl[p][3]);
                }
            #pragma unroll
            for (int mi = 0; mi < 4; ++mi) ldsm4(a[mi], pAl + mi * (16 * PADB) + kb);
            #pragma unroll
            for (int mi = 0; mi < 4; ++mi)
                #pragma unroll
                for (int p = 0; p < NLB; ++p) {
                    mma16816(acc[mi][p * 2],     a[mi], bh[p][0], bh[p][1]);
                    mma16816(acc[mi][p * 2 + 1], a[mi], bh[p][2], bh[p][3]);
                }
        }
    };

    issue(0, 0);
    issue(1, 1);
    #pragma unroll 1
    for (int t = 0; t < 4; ++t) {
        if (t < 3) asm volatile("cp.async.wait_group 1;" ::: "memory");
        else       asm volatile("cp.async.wait_group 0;" ::: "memory");
        __syncthreads();
        compute(t & 1);
        __syncthreads();
        if (t < 2) issue(t + 2, t & 1);
    }

    // ---- epilogue ----
    #pragma unroll
    for (int mi = 0; mi < 4; ++mi) {
        int r0 = m0 + wm * 64 + mi * 16 + (lane >> 2);
        #pragma unroll
        for (int nj = 0; nj < NFRAG; ++nj) {
            int c = wn * WARP_N + nj * 8 + (lane & 3) * 2;
            float bb0 = __ldg(&bias[c]);
            float bb1 = __ldg(&bias[c + 1]);
            const float* d = acc[mi][nj];
            float v00 = d[0] + bb0, v01 = d[1] + bb1;
            float v10 = d[2] + bb0, v11 = d[3] + bb1;
            if (RELU) {
                v00 = fmaxf(v00, 0.f); v01 = fmaxf(v01, 0.f);
                v10 = fmaxf(v10, 0.f); v11 = fmaxf(v11, 0.f);
            }
            if (r0 < NN) {
                *(float2*)(outF + (size_t)r0 * BN + c) = make_float2(v00, v01);
                if (SPLIT) {
                    __nv_bfloat162 H = __floats2bfloat162_rn(v00, v01);
                    __nv_bfloat162 L = __floats2bfloat162_rn(v00 - __bfloat162float(H.x),
                                                             v01 - __bfloat162float(H.y));
                    *(__nv_bfloat162*)(outHh + (size_t)r0 * DD + c) = H;
                    *(__nv_bfloat162*)(outHl + (size_t)r0 * DD + c) = L;
                }
            }
            if (r0 + 8 < NN) {
                *(float2*)(outF + (size_t)(r0 + 8) * BN + c) = make_float2(v10, v11);
                if (SPLIT) {
                    __nv_bfloat162 H = __floats2bfloat162_rn(v10, v11);
                    __nv_bfloat162 L = __floats2bfloat162_rn(v10 - __bfloat162float(H.x),
                                                             v11 - __bfloat162float(H.y));
                    *(__nv_bfloat162*)(outHh + (size_t)(r0 + 8) * DD + c) = H;
                    *(__nv_bfloat162*)(outHl + (size_t)(r0 + 8) * DD + c) = L;
                }
            }
        }
    }
}

// ================= launch =================
extern "C" void kernel_launch(void* const* d_in, const int* in_sizes, int n_in,
                              void* d_out, int out_size) {
    (void)in_sizes; (void)n_in; (void)out_size;
    const float* x  = (const float*)d_in[0];
    const int*   ei = (const int*)d_in[1];
    const float* ew = (const float*)d_in[2];
    const float* W0 = (const float*)d_in[3];
    const float* b0 = (const float*)d_in[4];
    const float* W1 = (const float*)d_in[5];
    const float* b1 = (const float*)d_in[6];
    const float* W2 = (const float*)d_in[7];
    const float* b2 = (const float*)d_in[8];
    float* out = (float*)d_out;

    void *p_cnt, *p_deg, *p_h;
    void *p_xhA, *p_xlA, *p_xhB, *p_xlB;
    void *p_wh0, *p_wl0, *p_wh1, *p_wl1, *p_wh2, *p_wl2;
    cudaGetSymbolAddress(&p_cnt, g_cnt);
    cudaGetSymbolAddress(&p_deg, g_deg);
    cudaGetSymbolAddress(&p_h,   g_h);
    cudaGetSymbolAddress(&p_xhA, g_xhA);
    cudaGetSymbolAddress(&p_xlA, g_xlA);
    cudaGetSymbolAddress(&p_xhB, g_xhB);
    cudaGetSymbolAddress(&p_xlB, g_xlB);
    cudaGetSymbolAddress(&p_wh0, g_Wh0);
    cudaGetSymbolAddress(&p_wl0, g_Wl0);
    cudaGetSymbolAddress(&p_wh1, g_Wh1);
    cudaGetSymbolAddress(&p_wl1, g_Wl1);
    cudaGetSymbolAddress(&p_wh2, g_Wh2);
    cudaGetSymbolAddress(&p_wl2, g_Wl2);
    float* h = (float*)p_h;

    const int SMEM128 = 2 * (2 * 128 * 144 + 2 * 128 * 144);   // 147456
    const int SMEM64  = 2 * (2 * 128 * 144 + 2 * 64 * 144);    // 110592
    cudaFuncSetAttribute(tgemm_kernel<128, true, true>,
                         cudaFuncAttributeMaxDynamicSharedMemorySize, SMEM128);
    cudaFuncSetAttribute(tgemm_kernel<64, false, false>,
                         cudaFuncAttributeMaxDynamicSharedMemorySize, SMEM64);

    cudaMemsetAsync(p_cnt, 0, NN * sizeof(int), 0);
    cudaMemsetAsync(p_deg, 0, NN * sizeof(float), 0);

    const int totW = 2 * 128 * KK + 64 * KK;
    prep_W<<<(totW + 255) / 256, 256>>>(W0, W1, W2);
    split_x<<<(NN * DD / 4 + 255) / 256, 256>>>(x);
    count_kernel<<<(NE + 255) / 256, 256>>>(ei, ew);
    scan_kernel<<<1, 1024>>>();
    fill_kernel<<<(NE + 255) / 256, 256>>>(ei, ew);

    const int aggBlocks  = (NN + 7) / 8;
    const int gemmBlocks = (NN + 127) / 128;

    // layer 0
    agg_kernel<<<aggBlocks, 256>>>(x);
    tgemm_kernel<128, true, true><<<gemmBlocks, 256, SMEM128>>>(
        (const __nv_bfloat16*)p_xhA, (const __nv_bfloat16*)p_xlA,
        (const __nv_bfloat16*)p_wh0, (const __nv_bfloat16*)p_wl0,
        b0, h, (__nv_bfloat16*)p_xhB, (__nv_bfloat16*)p_xlB);

    // layer 1
    agg_kernel<<<aggBlocks, 256>>>(h);
    tgemm_kernel<128, true, true><<<gemmBlocks, 256, SMEM128>>>(
        (const __nv_bfloat16*)p_xhB, (const __nv_bfloat16*)p_xlB,
        (const __nv_bfloat16*)p_wh1, (const __nv_bfloat16*)p_wl1,
        b1, h, (__nv_bfloat16*)p_xhA, (__nv_bfloat16*)p_xlA);

    // layer 2
    agg_kernel<<<aggBlocks, 256>>>(h);
    tgemm_kernel<64, false, false><<<gemmBlocks, 256, SMEM64>>>(
        (const __nv_bfloat16*)p_xhA, (const __nv_bfloat16*)p_xlA,
        (const __nv_bfloat16*)p_wh2, (const __nv_bfloat16*)p_wl2,
        b2, out, nullptr, nullptr);
}

// round 7
// speedup vs baseline: 1.6280x; 1.1404x over previous
#include <cuda_runtime.h>
#include <cuda_bf16.h>
#include <cstdint>
#include <cstddef>

#define NN   50000
#define NE   800000
#define DD   128
#define KK   256
#define NBLK 49          // ceil(NN/1024)

// ================= low-level helpers =================
__device__ __forceinline__ uint32_t smem_u32(const void* p) {
    uint32_t a;
    asm("{ .reg .u64 t; cvta.to.shared.u64 t, %1; cvt.u32.u64 %0, t; }" : "=r"(a) : "l"(p));
    return a;
}
__device__ __forceinline__ void ldsm4(uint32_t* r, uint32_t addr) {
    asm volatile("ldmatrix.sync.aligned.m8n8.x4.shared.b16 {%0,%1,%2,%3}, [%4];"
                 : "=r"(r[0]), "=r"(r[1]), "=r"(r[2]), "=r"(r[3]) : "r"(addr));
}
__device__ __forceinline__ void mma16816(float* d, const uint32_t* a, uint32_t b0, uint32_t b1) {
    asm volatile(
        "mma.sync.aligned.m16n8k16.row.col.f32.bf16.bf16.f32 "
        "{%0,%1,%2,%3}, {%4,%5,%6,%7}, {%8,%9}, {%0,%1,%2,%3};"
        : "+f"(d[0]), "+f"(d[1]), "+f"(d[2]), "+f"(d[3])
        : "r"(a[0]), "r"(a[1]), "r"(a[2]), "r"(a[3]), "r"(b0), "r"(b1));
}
__device__ __forceinline__ void cpa16(uint32_t dst, const void* src, int sz) {
    asm volatile("cp.async.cg.shared.global [%0], [%1], 16, %2;"
                 :: "r"(dst), "l"(src), "r"(sz));
}
#define CPA_COMMIT() asm volatile("cp.async.commit_group;" ::: "memory")

// ================= device scratch =================
__device__ int   g_cnt[NN];
__device__ int   g_off[NN + 1];
__device__ int   g_bsum[NBLK];
__device__ int   g_bpre[NBLK];
__device__ int   g_col[NE];
__device__ float g_wgt[NE];
__device__ float g_h[NN * DD];                       // fp32 hidden (for agg gather)
__device__ __nv_bfloat16 g_xhA[NN * DD], g_xlA[NN * DD];   // layer input split (ping)
__device__ __nv_bfloat16 g_xhB[NN * DD], g_xlB[NN * DD];   // (pong)
__device__ __nv_bfloat16 g_ah[NN * DD],  g_al[NN * DD];    // agg split
__device__ __nv_bfloat16 g_Wh0[128 * KK], g_Wl0[128 * KK];
__device__ __nv_bfloat16 g_Wh1[128 * KK], g_Wl1[128 * KK];
__device__ __nv_bfloat16 g_Wh2[64 * KK],  g_Wl2[64 * KK];

// ================= weight split (plain [n][k] layout) =================
__global__ void prep_W(const float* __restrict__ W0,
                       const float* __restrict__ W1,
                       const float* __restrict__ W2) {
    int i = blockIdx.x * 256 + threadIdx.x;
    const int L = 128 * KK;
    float w; __nv_bfloat16 *dh, *dl; int j;
    if (i < L)               { j = i;         w = W0[j]; dh = g_Wh0; dl = g_Wl0; }
    else if (i < 2 * L)      { j = i - L;     w = W1[j]; dh = g_Wh1; dl = g_Wl1; }
    else if (i < 2 * L + 64 * KK) { j = i - 2 * L; w = W2[j]; dh = g_Wh2; dl = g_Wl2; }
    else return;
    __nv_bfloat16 hi = __float2bfloat16(w);
    __nv_bfloat16 lo = __float2bfloat16(w - __bfloat162float(hi));
    dh[j] = hi;
    dl[j] = lo;
}

// ================= split x (once) =================
__global__ void split_x(const float* __restrict__ x) {
    int i = blockIdx.x * 256 + threadIdx.x;         // float4 index
    if (i >= NN * DD / 4) return;
    float4 v = ((const float4*)x)[i];
    __nv_bfloat162 h0 = __floats2bfloat162_rn(v.x, v.y);
    __nv_bfloat162 h1 = __floats2bfloat162_rn(v.z, v.w);
    __nv_bfloat162 l0 = __floats2bfloat162_rn(v.x - __bfloat162float(h0.x),
                                              v.y - __bfloat162float(h0.y));
    __nv_bfloat162 l1 = __floats2bfloat162_rn(v.z - __bfloat162float(h1.x),
                                              v.w - __bfloat162float(h1.y));
    ((__nv_bfloat162*)g_xhA)[i * 2]     = h0;
    ((__nv_bfloat162*)g_xhA)[i * 2 + 1] = h1;
    ((__nv_bfloat162*)g_xlA)[i * 2]     = l0;
    ((__nv_bfloat162*)g_xlA)[i * 2 + 1] = l1;
}

// ================= CSR build =================
__global__ void count_kernel(const int* __restrict__ ei) {
    int e4 = blockIdx.x * blockDim.x + threadIdx.x;   // 4 edges per thread
    if (e4 >= NE / 4) return;
    int4 r = ((const int4*)ei)[e4];
    atomicAdd(&g_cnt[r.x], 1);
    atomicAdd(&g_cnt[r.y], 1);
    atomicAdd(&g_cnt[r.z], 1);
    atomicAdd(&g_cnt[r.w], 1);
}

// -- 3-phase multi-block scan --
__global__ void scan_p1() {                 // grid NBLK x 1024: block reduce
    __shared__ int ws[32];
    int i = blockIdx.x * 1024 + threadIdx.x;
    int v = (i < NN) ? g_cnt[i] : 0;
    #pragma unroll
    for (int o = 16; o > 0; o >>= 1) v += __shfl_down_sync(0xffffffffu, v, o);
    if ((threadIdx.x & 31) == 0) ws[threadIdx.x >> 5] = v;
    __syncthreads();
    if (threadIdx.x < 32) {
        int t = ws[threadIdx.x];
        #pragma unroll
        for (int o = 16; o > 0; o >>= 1) t += __shfl_down_sync(0xffffffffu, t, o);
        if (threadIdx.x == 0) g_bsum[blockIdx.x] = t;
    }
}

__global__ void scan_p2() {                 // 1 block of 64: exclusive scan of NBLK sums
    int lane = threadIdx.x & 31;
    int wid  = threadIdx.x >> 5;
    __shared__ int wtot;
    int v = (threadIdx.x < NBLK) ? g_bsum[threadIdx.x] : 0;
    int incl = v;
    #pragma unroll
    for (int o = 1; o < 32; o <<= 1) {
        int t = __shfl_up_sync(0xffffffffu, incl, o);
        if (lane >= o) incl += t;
    }
    if (wid == 0 && lane == 31) wtot = incl;
    __syncthreads();
    int excl = incl - v + (wid ? wtot : 0);
    if (threadIdx.x < NBLK) g_bpre[threadIdx.x] = excl;
    if (threadIdx.x == 0) g_off[NN] = NE;
}

__global__ void scan_p3() {                 // grid NBLK x 1024: local scan + base
    __shared__ int ws[32];
    const int tid = threadIdx.x, lane = tid & 31, wid = tid >> 5;
    int i = blockIdx.x * 1024 + tid;
    int v = (i < NN) ? g_cnt[i] : 0;
    int incl = v;
    #pragma unroll
    for (int o = 1; o < 32; o <<= 1) {
        int t = __shfl_up_sync(0xffffffffu, incl, o);
        if (lane >= o) incl += t;
    }
    if (lane == 31) ws[wid] = incl;
    __syncthreads();
    if (wid == 0) {
        int wv = (lane < 32) ? ws[lane] : 0;
        int s = wv;
        #pragma unroll
        for (int o = 1; o < 32; o <<= 1) {
            int t = __shfl_up_sync(0xffffffffu, s, o);
            if (lane >= o) s += t;
        }
        ws[lane] = s - wv;
    }
    __syncthreads();
    int o = g_bpre[blockIdx.x] + ws[wid] + incl - v;
    if (i < NN) { g_off[i] = o; g_cnt[i] = o; }
}

__global__ void fill_kernel(const int* __restrict__ ei, const float* __restrict__ ew) {
    int e4 = blockIdx.x * blockDim.x + threadIdx.x;
    if (e4 >= NE / 4) return;
    int4   r = ((const int4*)ei)[e4];
    int4   c = ((const int4*)(ei + NE))[e4];
    float4 w = ((const float4*)ew)[e4];
    int p;
    p = atomicAdd(&g_cnt[r.x], 1); g_col[p] = c.x; g_wgt[p] = w.x;
    p = atomicAdd(&g_cnt[r.y], 1); g_col[p] = c.y; g_wgt[p] = w.y;
    p = atomicAdd(&g_cnt[r.z], 1); g_col[p] = c.z; g_wgt[p] = w.z;
    p = atomicAdd(&g_cnt[r.w], 1); g_col[p] = c.w; g_wgt[p] = w.w;
}

// ================= aggregation: warp per node, inline deg, bf16-split output ==
__global__ void agg_kernel(const float* __restrict__ xin) {
    int gw = (blockIdx.x * blockDim.x + threadIdx.x) >> 5;
    if (gw >= NN) return;
    const int lane = threadIdx.x & 31;
    const int s = g_off[gw];
    const int e = g_off[gw + 1];
    float4 acc = make_float4(0.f, 0.f, 0.f, 0.f);
    float wsum = 0.f;
    for (int base = s; base < e; base += 32) {
        int nn = min(32, e - base);
        int c = 0; float w = 0.f;
        if (lane < nn) { c = g_col[base + lane]; w = g_wgt[base + lane]; }
        wsum += w;
        for (int j = 0; j < nn; ++j) {
            int cj = __shfl_sync(0xffffffffu, c, j);
            float wj = __shfl_sync(0xffffffffu, w, j);
            float4 v = *(const float4*)(xin + (size_t)cj * DD + lane * 4);
            acc.x = fmaf(v.x, wj, acc.x);
            acc.y = fmaf(v.y, wj, acc.y);
            acc.z = fmaf(v.z, wj, acc.z);
            acc.w = fmaf(v.w, wj, acc.w);
        }
    }
    #pragma unroll
    for (int o = 16; o > 0; o >>= 1) wsum += __shfl_xor_sync(0xffffffffu, wsum, o);
    float invd = 1.0f / fmaxf(wsum, 1.0f);
    float v0 = acc.x * invd, v1 = acc.y * invd, v2 = acc.z * invd, v3 = acc.w * invd;
    __nv_bfloat162 h01 = __floats2bfloat162_rn(v0, v1);
    __nv_bfloat162 h23 = __floats2bfloat162_rn(v2, v3);
    __nv_bfloat162 l01 = __floats2bfloat162_rn(v0 - __bfloat162float(h01.x),
                                               v1 - __bfloat162float(h01.y));
    __nv_bfloat162 l23 = __floats2bfloat162_rn(v2 - __bfloat162float(h23.x),
                                               v3 - __bfloat162float(h23.y));
    __nv_bfloat162* oh = (__nv_bfloat162*)g_ah + (size_t)gw * 64 + lane * 2;
    __nv_bfloat162* ol = (__nv_bfloat162*)g_al + (size_t)gw * 64 + lane * 2;
    oh[0] = h01; oh[1] = h23;
    ol[0] = l01; ol[1] = l23;
}

// ================= HMMA GEMM: out = [X|Agg] @ W^T + b =================
template <int BN, bool RELU, bool SPLIT>
__global__ void __launch_bounds__(256, 1) tgemm_kernel(
    const __nv_bfloat16* __restrict__ Xh, const __nv_bfloat16* __restrict__ Xl,
    const __nv_bfloat16* __restrict__ Wh, const __nv_bfloat16* __restrict__ Wl,
    const float* __restrict__ bias,
    float* __restrict__ outF,
    __nv_bfloat16* __restrict__ outHh, __nv_bfloat16* __restrict__ outHl)
{
    extern __shared__ __align__(16) char smem[];
    constexpr int PADB  = 144;
    constexpr int ASZ   = 128 * PADB;
    constexpr int BSZ   = BN * PADB;
    constexpr int STAGE = 2 * ASZ + 2 * BSZ;
    constexpr int WARP_N = BN / 4;
    constexpr int NFRAG  = WARP_N / 8;
    constexpr int NLB    = NFRAG / 2;
    constexpr int BLOADS = (BN * 8) / 256;

    const int tid  = threadIdx.x;
    const int lane = tid & 31;
    const int wid  = tid >> 5;
    const int wm   = wid >> 2;
    const int wn   = wid & 3;
    const int m0   = blockIdx.x * 128;

    const uint32_t sbase = smem_u32(smem);
    const uint32_t offA = (uint32_t)((wm * 64 + (lane & 15)) * PADB + (lane >> 4) * 16);
    const uint32_t offB = (uint32_t)((wn * WARP_N + (lane & 7) + ((lane >> 4) << 3)) * PADB
                                     + (lane & 8) * 2);

    float acc[4][NFRAG][4];
    #pragma unroll
    for (int i = 0; i < 4; ++i)
        #pragma unroll
        for (int j = 0; j < NFRAG; ++j)
            #pragma unroll
            for (int q = 0; q < 4; ++q) acc[i][j][q] = 0.f;

    auto issue = [&](int t, int b) {
        const uint32_t st = sbase + b * STAGE;
        const __nv_bfloat16* axh = (t < 2) ? Xh : g_ah;
        const __nv_bfloat16* axl = (t < 2) ? Xl : g_al;
        const int colb = (t & 1) * 64;
        #pragma unroll
        for (int i = 0; i < 4; ++i) {
            int idx = tid + i * 256;
            int row = idx >> 3, ch = idx & 7;
            int gr = m0 + row;
            int ok = (gr < NN) ? 16 : 0;
            int grc = (gr < NN) ? gr : 0;
            size_t go = (size_t)grc * DD + colb + ch * 8;
            uint32_t sa = (uint32_t)(row * PADB + ch * 16);
            cpa16(st + sa,        axh + go, ok);
            cpa16(st + ASZ + sa,  axl + go, ok);
        }
        #pragma unroll
        for (int i = 0; i < BLOADS; ++i) {
            int idx = tid + i * 256;
            int row = idx >> 3, ch = idx & 7;
            size_t go = (size_t)row * KK + t * 64 + ch * 8;
            uint32_t sa = (uint32_t)(row * PADB + ch * 16);
            cpa16(st + 2 * ASZ + sa,       Wh + go, 16);
            cpa16(st + 2 * ASZ + BSZ + sa, Wl + go, 16);
        }
        CPA_COMMIT();
    };

    auto compute = [&](int b) {
        const uint32_t st  = sbase + b * STAGE;
        const uint32_t pAh = st + offA;
        const uint32_t pAl = st + ASZ + offA;
        const uint32_t pBh = st + 2 * ASZ + offB;
        const uint32_t pBl = st + 2 * ASZ + BSZ + offB;
        #pragma unroll
        for (int kk = 0; kk < 4; ++kk) {
            const int kb = kk * 32;
            uint32_t a[4][4];
            #pragma unroll
            for (int mi = 0; mi < 4; ++mi) ldsm4(a[mi], pAh + mi * (16 * PADB) + kb);
            uint32_t bh[NLB][4];
            #pragma unroll
            for (int p = 0; p < NLB; ++p) ldsm4(bh[p], pBh + p * (16 * PADB) + kb);
            #pragma unroll
            for (int mi = 0; mi < 4; ++mi)
                #pragma unroll
                for (int p = 0; p < NLB; ++p) {
                    mma16816(acc[mi][p * 2],     a[mi], bh[p][0], bh[p][1]);
                    mma16816(acc[mi][p * 2 + 1], a[mi], bh[p][2], bh[p][3]);
                }
            uint32_t bl[NLB][4];
            #pragma unroll
            for (int p = 0; p < NLB; ++p) ldsm4(bl[p], pBl + p * (16 * PADB) + kb);
            #pragma unroll
            for (int mi = 0; mi < 4; ++mi)
                #pragma unroll
                for (int p = 0; p < NLB; ++p) {
                    mma16816(acc[mi][p * 2],     a[mi], bl[p][0], bl[p][1]);
                    mma16816(acc[mi][p * 2 + 1], a[mi], bl[p][2], bl[p][3]);
                }
            #pragma unroll
            for (int mi = 0; mi < 4; ++mi) ldsm4(a[mi], pAl + mi * (16 * PADB) + kb);
            #pragma unroll
            for (int mi = 0; mi < 4; ++mi)
                #pragma unroll
                for (int p = 0; p < NLB; ++p) {
                    mma16816(acc[mi][p * 2],     a[mi], bh[p][0], bh[p][1]);
                    mma16816(acc[mi][p * 2 + 1], a[mi], bh[p][2], bh[p][3]);
                }
        }
    };

    issue(0, 0);
    issue(1, 1);
    #pragma unroll 1
    for (int t = 0; t < 4; ++t) {
        if (t < 3) asm volatile("cp.async.wait_group 1;" ::: "memory");
        else       asm volatile("cp.async.wait_group 0;" ::: "memory");
        __syncthreads();
        compute(t & 1);
        __syncthreads();
        if (t < 2) issue(t + 2, t & 1);
    }

    #pragma unroll
    for (int mi = 0; mi < 4; ++mi) {
        int r0 = m0 + wm * 64 + mi * 16 + (lane >> 2);
        #pragma unroll
        for (int nj = 0; nj < NFRAG; ++nj) {
            int c = wn * WARP_N + nj * 8 + (lane & 3) * 2;
            float bb0 = __ldg(&bias[c]);
            float bb1 = __ldg(&bias[c + 1]);
            const float* d = acc[mi][nj];
            float v00 = d[0] + bb0, v01 = d[1] + bb1;
            float v10 = d[2] + bb0, v11 = d[3] + bb1;
            if (RELU) {
                v00 = fmaxf(v00, 0.f); v01 = fmaxf(v01, 0.f);
                v10 = fmaxf(v10, 0.f); v11 = fmaxf(v11, 0.f);
            }
            if (r0 < NN) {
                *(float2*)(outF + (size_t)r0 * BN + c) = make_float2(v00, v01);
                if (SPLIT) {
                    __nv_bfloat162 H = __floats2bfloat162_rn(v00, v01);
                    __nv_bfloat162 L = __floats2bfloat162_rn(v00 - __bfloat162float(H.x),
                                                             v01 - __bfloat162float(H.y));
                    *(__nv_bfloat162*)(outHh + (size_t)r0 * DD + c) = H;
                    *(__nv_bfloat162*)(outHl + (size_t)r0 * DD + c) = L;
                }
            }
            if (r0 + 8 < NN) {
                *(float2*)(outF + (size_t)(r0 + 8) * BN + c) = make_float2(v10, v11);
                if (SPLIT) {
                    __nv_bfloat162 H = __floats2bfloat162_rn(v10, v11);
                    __nv_bfloat162 L = __floats2bfloat162_rn(v10 - __bfloat162float(H.x),
                                                             v11 - __bfloat162float(H.y));
                    *(__nv_bfloat162*)(outHh + (size_t)(r0 + 8) * DD + c) = H;
                    *(__nv_bfloat162*)(outHl + (size_t)(r0 + 8) * DD + c) = L;
                }
            }
        }
    }
}

// ================= launch =================
extern "C" void kernel_launch(void* const* d_in, const int* in_sizes, int n_in,
                              void* d_out, int out_size) {
    (void)in_sizes; (void)n_in; (void)out_size;
    const float* x  = (const float*)d_in[0];
    const int*   ei = (const int*)d_in[1];
    const float* ew = (const float*)d_in[2];
    const float* W0 = (const float*)d_in[3];
    const float* b0 = (const float*)d_in[4];
    const float* W1 = (const float*)d_in[5];
    const float* b1 = (const float*)d_in[6];
    const float* W2 = (const float*)d_in[7];
    const float* b2 = (const float*)d_in[8];
    float* out = (float*)d_out;

    void *p_cnt, *p_h;
    void *p_xhA, *p_xlA, *p_xhB, *p_xlB;
    void *p_wh0, *p_wl0, *p_wh1, *p_wl1, *p_wh2, *p_wl2;
    cudaGetSymbolAddress(&p_cnt, g_cnt);
    cudaGetSymbolAddress(&p_h,   g_h);
    cudaGetSymbolAddress(&p_xhA, g_xhA);
    cudaGetSymbolAddress(&p_xlA, g_xlA);
    cudaGetSymbolAddress(&p_xhB, g_xhB);
    cudaGetSymbolAddress(&p_xlB, g_xlB);
    cudaGetSymbolAddress(&p_wh0, g_Wh0);
    cudaGetSymbolAddress(&p_wl0, g_Wl0);
    cudaGetSymbolAddress(&p_wh1, g_Wh1);
    cudaGetSymbolAddress(&p_wl1, g_Wl1);
    cudaGetSymbolAddress(&p_wh2, g_Wh2);
    cudaGetSymbolAddress(&p_wl2, g_Wl2);
    float* h = (float*)p_h;

    const int SMEM128 = 2 * (2 * 128 * 144 + 2 * 128 * 144);
    const int SMEM64  = 2 * (2 * 128 * 144 + 2 * 64 * 144);
    cudaFuncSetAttribute(tgemm_kernel<128, true, true>,
                         cudaFuncAttributeMaxDynamicSharedMemorySize, SMEM128);
    cudaFuncSetAttribute(tgemm_kernel<64, false, false>,
                         cudaFuncAttributeMaxDynamicSharedMemorySize, SMEM64);

    cudaMemsetAsync(p_cnt, 0, NN * sizeof(int), 0);

    const int totW = 2 * 128 * KK + 64 * KK;
    prep_W<<<(totW + 255) / 256, 256>>>(W0, W1, W2);
    split_x<<<(NN * DD / 4 + 255) / 256, 256>>>(x);
    count_kernel<<<(NE / 4 + 255) / 256, 256>>>(ei);
    scan_p1<<<NBLK, 1024>>>();
    scan_p2<<<1, 64>>>();
    scan_p3<<<NBLK, 1024>>>();
    fill_kernel<<<(NE / 4 + 255) / 256, 256>>>(ei, ew);

    const int aggBlocks  = (NN + 7) / 8;
    const int gemmBlocks = (NN + 127) / 128;

    // layer 0
    agg_kernel<<<aggBlocks, 256>>>(x);
    tgemm_kernel<128, true, true><<<gemmBlocks, 256, SMEM128>>>(
        (const __nv_bfloat16*)p_xhA, (const __nv_bfloat16*)p_xlA,
        (const __nv_bfloat16*)p_wh0, (const __nv_bfloat16*)p_wl0,
        b0, h, (__nv_bfloat16*)p_xhB, (__nv_bfloat16*)p_xlB);

    // layer 1
    agg_kernel<<<aggBlocks, 256>>>(h);
    tgemm_kernel<128, true, true><<<gemmBlocks, 256, SMEM128>>>(
        (const __nv_bfloat16*)p_xhB, (const __nv_bfloat16*)p_xlB,
        (const __nv_bfloat16*)p_wh1, (const __nv_bfloat16*)p_wl1,
        b1, h, (__nv_bfloat16*)p_xhA, (__nv_bfloat16*)p_xlA);

    // layer 2
    agg_kernel<<<aggBlocks, 256>>>(h);
    tgemm_kernel<64, false, false><<<gemmBlocks, 256, SMEM64>>>(
        (const __nv_bfloat16*)p_xhA, (const __nv_bfloat16*)p_xlA,
        (const __nv_bfloat16*)p_wh2, (const __nv_bfloat16*)p_wl2,
        b2, out, nullptr, nullptr);
}

// round 8
// speedup vs baseline: 1.7697x; 1.0871x over previous
#include <cuda_runtime.h>
#include <cuda_bf16.h>
#include <cuda_fp16.h>
#include <cstdint>
#include <cstddef>

#define NN   50000
#define NE   800000
#define DD   128
#define KK   256
#define NBLK 49          // ceil(NN/1024)

// ================= low-level helpers =================
__device__ __forceinline__ uint32_t smem_u32(const void* p) {
    uint32_t a;
    asm("{ .reg .u64 t; cvta.to.shared.u64 t, %1; cvt.u32.u64 %0, t; }" : "=r"(a) : "l"(p));
    return a;
}
__device__ __forceinline__ void ldsm4(uint32_t* r, uint32_t addr) {
    asm volatile("ldmatrix.sync.aligned.m8n8.x4.shared.b16 {%0,%1,%2,%3}, [%4];"
                 : "=r"(r[0]), "=r"(r[1]), "=r"(r[2]), "=r"(r[3]) : "r"(addr));
}
__device__ __forceinline__ void mma16816(float* d, const uint32_t* a, uint32_t b0, uint32_t b1) {
    asm volatile(
        "mma.sync.aligned.m16n8k16.row.col.f32.bf16.bf16.f32 "
        "{%0,%1,%2,%3}, {%4,%5,%6,%7}, {%8,%9}, {%0,%1,%2,%3};"
        : "+f"(d[0]), "+f"(d[1]), "+f"(d[2]), "+f"(d[3])
        : "r"(a[0]), "r"(a[1]), "r"(a[2]), "r"(a[3]), "r"(b0), "r"(b1));
}
__device__ __forceinline__ void cpa16(uint32_t dst, const void* src, int sz) {
    asm volatile("cp.async.cg.shared.global [%0], [%1], 16, %2;"
                 :: "r"(dst), "l"(src), "r"(sz));
}
#define CPA_COMMIT() asm volatile("cp.async.commit_group;" ::: "memory")

// ================= device scratch =================
__device__ int   g_cnt[NN];
__device__ int   g_off[NN + 1];
__device__ int   g_bsum[NBLK];
__device__ int   g_bpre[NBLK];
__device__ int   g_col[NE];
__device__ float g_wgt[NE];
__device__ __half g_xf16[NN * DD];                   // fp16 x (agg gather, layer 0)
__device__ __half g_hf16[NN * DD];                   // fp16 hidden (agg gather, layers 1/2)
__device__ __nv_bfloat16 g_xhA[NN * DD], g_xlA[NN * DD];   // GEMM input split (ping)
__device__ __nv_bfloat16 g_xhB[NN * DD], g_xlB[NN * DD];   // (pong)
__device__ __nv_bfloat16 g_ah[NN * DD],  g_al[NN * DD];    // agg split
__device__ __nv_bfloat16 g_Wh0[128 * KK], g_Wl0[128 * KK];
__device__ __nv_bfloat16 g_Wh1[128 * KK], g_Wl1[128 * KK];
__device__ __nv_bfloat16 g_Wh2[64 * KK],  g_Wl2[64 * KK];

// ================= weight split (plain [n][k] layout) =================
__global__ void prep_W(const float* __restrict__ W0,
                       const float* __restrict__ W1,
                       const float* __restrict__ W2) {
    int i = blockIdx.x * 256 + threadIdx.x;
    const int L = 128 * KK;
    float w; __nv_bfloat16 *dh, *dl; int j;
    if (i < L)               { j = i;         w = W0[j]; dh = g_Wh0; dl = g_Wl0; }
    else if (i < 2 * L)      { j = i - L;     w = W1[j]; dh = g_Wh1; dl = g_Wl1; }
    else if (i < 2 * L + 64 * KK) { j = i - 2 * L; w = W2[j]; dh = g_Wh2; dl = g_Wl2; }
    else return;
    __nv_bfloat16 hi = __float2bfloat16(w);
    __nv_bfloat16 lo = __float2bfloat16(w - __bfloat162float(hi));
    dh[j] = hi;
    dl[j] = lo;
}

// ================= split x (once): bf16 hi/lo + fp16 shadow =================
__global__ void split_x(const float* __restrict__ x) {
    int i = blockIdx.x * 256 + threadIdx.x;         // float4 index
    if (i >= NN * DD / 4) return;
    float4 v = ((const float4*)x)[i];
    __nv_bfloat162 h0 = __floats2bfloat162_rn(v.x, v.y);
    __nv_bfloat162 h1 = __floats2bfloat162_rn(v.z, v.w);
    __nv_bfloat162 l0 = __floats2bfloat162_rn(v.x - __bfloat162float(h0.x),
                                              v.y - __bfloat162float(h0.y));
    __nv_bfloat162 l1 = __floats2bfloat162_rn(v.z - __bfloat162float(h1.x),
                                              v.w - __bfloat162float(h1.y));
    ((__nv_bfloat162*)g_xhA)[i * 2]     = h0;
    ((__nv_bfloat162*)g_xhA)[i * 2 + 1] = h1;
    ((__nv_bfloat162*)g_xlA)[i * 2]     = l0;
    ((__nv_bfloat162*)g_xlA)[i * 2 + 1] = l1;
    ((__half2*)g_xf16)[i * 2]     = __floats2half2_rn(v.x, v.y);
    ((__half2*)g_xf16)[i * 2 + 1] = __floats2half2_rn(v.z, v.w);
}

// ================= CSR build =================
__global__ void count_kernel(const int* __restrict__ ei) {
    int e4 = blockIdx.x * blockDim.x + threadIdx.x;   // 4 edges per thread
    if (e4 >= NE / 4) return;
    int4 r = ((const int4*)ei)[e4];
    atomicAdd(&g_cnt[r.x], 1);
    atomicAdd(&g_cnt[r.y], 1);
    atomicAdd(&g_cnt[r.z], 1);
    atomicAdd(&g_cnt[r.w], 1);
}

// -- 3-phase multi-block scan --
__global__ void scan_p1() {
    __shared__ int ws[32];
    int i = blockIdx.x * 1024 + threadIdx.x;
    int v = (i < NN) ? g_cnt[i] : 0;
    #pragma unroll
    for (int o = 16; o > 0; o >>= 1) v += __shfl_down_sync(0xffffffffu, v, o);
    if ((threadIdx.x & 31) == 0) ws[threadIdx.x >> 5] = v;
    __syncthreads();
    if (threadIdx.x < 32) {
        int t = ws[threadIdx.x];
        #pragma unroll
        for (int o = 16; o > 0; o >>= 1) t += __shfl_down_sync(0xffffffffu, t, o);
        if (threadIdx.x == 0) g_bsum[blockIdx.x] = t;
    }
}

__global__ void scan_p2() {
    int lane = threadIdx.x & 31;
    int wid  = threadIdx.x >> 5;
    __shared__ int wtot;
    int v = (threadIdx.x < NBLK) ? g_bsum[threadIdx.x] : 0;
    int incl = v;
    #pragma unroll
    for (int o = 1; o < 32; o <<= 1) {
        int t = __shfl_up_sync(0xffffffffu, incl, o);
        if (lane >= o) incl += t;
    }
    if (wid == 0 && lane == 31) wtot = incl;
    __syncthreads();
    int excl = incl - v + (wid ? wtot : 0);
    if (threadIdx.x < NBLK) g_bpre[threadIdx.x] = excl;
    if (threadIdx.x == 0) g_off[NN] = NE;
}

__global__ void scan_p3() {
    __shared__ int ws[32];
    const int tid = threadIdx.x, lane = tid & 31, wid = tid >> 5;
    int i = blockIdx.x * 1024 + tid;
    int v = (i < NN) ? g_cnt[i] : 0;
    int incl = v;
    #pragma unroll
    for (int o = 1; o < 32; o <<= 1) {
        int t = __shfl_up_sync(0xffffffffu, incl, o);
        if (lane >= o) incl += t;
    }
    if (lane == 31) ws[wid] = incl;
    __syncthreads();
    if (wid == 0) {
        int wv = (lane < 32) ? ws[lane] : 0;
        int s = wv;
        #pragma unroll
        for (int o = 1; o < 32; o <<= 1) {
            int t = __shfl_up_sync(0xffffffffu, s, o);
            if (lane >= o) s += t;
        }
        ws[lane] = s - wv;
    }
    __syncthreads();
    int o = g_bpre[blockIdx.x] + ws[wid] + incl - v;
    if (i < NN) { g_off[i] = o; g_cnt[i] = o; }
}

__global__ void fill_kernel(const int* __restrict__ ei, const float* __restrict__ ew) {
    int e4 = blockIdx.x * blockDim.x + threadIdx.x;
    if (e4 >= NE / 4) return;
    int4   r = ((const int4*)ei)[e4];
    int4   c = ((const int4*)(ei + NE))[e4];
    float4 w = ((const float4*)ew)[e4];
    int p;
    p = atomicAdd(&g_cnt[r.x], 1); g_col[p] = c.x; g_wgt[p] = w.x;
    p = atomicAdd(&g_cnt[r.y], 1); g_col[p] = c.y; g_wgt[p] = w.y;
    p = atomicAdd(&g_cnt[r.z], 1); g_col[p] = c.z; g_wgt[p] = w.z;
    p = atomicAdd(&g_cnt[r.w], 1); g_col[p] = c.w; g_wgt[p] = w.w;
}

// ======= aggregation: warp per node, fp16 gather, fp32 accum, bf16-split out ==
__global__ void agg_kernel(const __half* __restrict__ xin) {
    int gw = (blockIdx.x * blockDim.x + threadIdx.x) >> 5;
    if (gw >= NN) return;
    const int lane = threadIdx.x & 31;
    const int s = g_off[gw];
    const int e = g_off[gw + 1];
    float4 acc = make_float4(0.f, 0.f, 0.f, 0.f);
    float wsum = 0.f;
    for (int base = s; base < e; base += 32) {
        int nn = min(32, e - base);
        int c = 0; float w = 0.f;
        if (lane < nn) { c = g_col[base + lane]; w = g_wgt[base + lane]; }
        wsum += w;
        for (int j = 0; j < nn; ++j) {
            int cj = __shfl_sync(0xffffffffu, c, j);
            float wj = __shfl_sync(0xffffffffu, w, j);
            uint2 u = *(const uint2*)(xin + (size_t)cj * DD + lane * 4);
            float2 f01 = __half22float2(*(const __half2*)&u.x);
            float2 f23 = __half22float2(*(const __half2*)&u.y);
            acc.x = fmaf(f01.x, wj, acc.x);
            acc.y = fmaf(f01.y, wj, acc.y);
            acc.z = fmaf(f23.x, wj, acc.z);
            acc.w = fmaf(f23.y, wj, acc.w);
        }
    }
    #pragma unroll
    for (int o = 16; o > 0; o >>= 1) wsum += __shfl_xor_sync(0xffffffffu, wsum, o);
    float invd = 1.0f / fmaxf(wsum, 1.0f);
    float v0 = acc.x * invd, v1 = acc.y * invd, v2 = acc.z * invd, v3 = acc.w * invd;
    __nv_bfloat162 h01 = __floats2bfloat162_rn(v0, v1);
    __nv_bfloat162 h23 = __floats2bfloat162_rn(v2, v3);
    __nv_bfloat162 l01 = __floats2bfloat162_rn(v0 - __bfloat162float(h01.x),
                                               v1 - __bfloat162float(h01.y));
    __nv_bfloat162 l23 = __floats2bfloat162_rn(v2 - __bfloat162float(h23.x),
                                               v3 - __bfloat162float(h23.y));
    __nv_bfloat162* oh = (__nv_bfloat162*)g_ah + (size_t)gw * 64 + lane * 2;
    __nv_bfloat162* ol = (__nv_bfloat162*)g_al + (size_t)gw * 64 + lane * 2;
    oh[0] = h01; oh[1] = h23;
    ol[0] = l01; ol[1] = l23;
}

// ================= HMMA GEMM: out = [X|Agg] @ W^T + b =================
// SPLIT=true (hidden layers): writes bf16 hi/lo (next GEMM input) + fp16 (next agg).
// SPLIT=false (final layer): writes fp32 to outF.
template <int BN, bool RELU, bool SPLIT>
__global__ void __launch_bounds__(256, 1) tgemm_kernel(
    const __nv_bfloat16* __restrict__ Xh, const __nv_bfloat16* __restrict__ Xl,
    const __nv_bfloat16* __restrict__ Wh, const __nv_bfloat16* __restrict__ Wl,
    const float* __restrict__ bias,
    float* __restrict__ outF,
    __nv_bfloat16* __restrict__ outHh, __nv_bfloat16* __restrict__ outHl,
    __half* __restrict__ outH16)
{
    extern __shared__ __align__(16) char smem[];
    constexpr int PADB  = 144;
    constexpr int ASZ   = 128 * PADB;
    constexpr int BSZ   = BN * PADB;
    constexpr int STAGE = 2 * ASZ + 2 * BSZ;
    constexpr int WARP_N = BN / 4;
    constexpr int NFRAG  = WARP_N / 8;
    constexpr int NLB    = NFRAG / 2;
    constexpr int BLOADS = (BN * 8) / 256;

    const int tid  = threadIdx.x;
    const int lane = tid & 31;
    const int wid  = tid >> 5;
    const int wm   = wid >> 2;
    const int wn   = wid & 3;
    const int m0   = blockIdx.x * 128;

    const uint32_t sbase = smem_u32(smem);
    const uint32_t offA = (uint32_t)((wm * 64 + (lane & 15)) * PADB + (lane >> 4) * 16);
    const uint32_t offB = (uint32_t)((wn * WARP_N + (lane & 7) + ((lane >> 4) << 3)) * PADB
                                     + (lane & 8) * 2);

    float acc[4][NFRAG][4];
    #pragma unroll
    for (int i = 0; i < 4; ++i)
        #pragma unroll
        for (int j = 0; j < NFRAG; ++j)
            #pragma unroll
            for (int q = 0; q < 4; ++q) acc[i][j][q] = 0.f;

    auto issue = [&](int t, int b) {
        const uint32_t st = sbase + b * STAGE;
        const __nv_bfloat16* axh = (t < 2) ? Xh : g_ah;
        const __nv_bfloat16* axl = (t < 2) ? Xl : g_al;
        const int colb = (t & 1) * 64;
        #pragma unroll
        for (int i = 0; i < 4; ++i) {
            int idx = tid + i * 256;
            int row = idx >> 3, ch = idx & 7;
            int gr = m0 + row;
            int ok = (gr < NN) ? 16 : 0;
            int grc = (gr < NN) ? gr : 0;
            size_t go = (size_t)grc * DD + colb + ch * 8;
            uint32_t sa = (uint32_t)(row * PADB + ch * 16);
            cpa16(st + sa,        axh + go, ok);
            cpa16(st + ASZ + sa,  axl + go, ok);
        }
        #pragma unroll
        for (int i = 0; i < BLOADS; ++i) {
            int idx = tid + i * 256;
            int row = idx >> 3, ch = idx & 7;
            size_t go = (size_t)row * KK + t * 64 + ch * 8;
            uint32_t sa = (uint32_t)(row * PADB + ch * 16);
            cpa16(st + 2 * ASZ + sa,       Wh + go, 16);
            cpa16(st + 2 * ASZ + BSZ + sa, Wl + go, 16);
        }
        CPA_COMMIT();
    };

    auto compute = [&](int b) {
        const uint32_t st  = sbase + b * STAGE;
        const uint32_t pAh = st + offA;
        const uint32_t pAl = st + ASZ + offA;
        const uint32_t pBh = st + 2 * ASZ + offB;
        const uint32_t pBl = st + 2 * ASZ + BSZ + offB;
        #pragma unroll
        for (int kk = 0; kk < 4; ++kk) {
            const int kb = kk * 32;
            uint32_t a[4][4];
            #pragma unroll
            for (int mi = 0; mi < 4; ++mi) ldsm4(a[mi], pAh + mi * (16 * PADB) + kb);
            uint32_t bh[NLB][4];
            #pragma unroll
            for (int p = 0; p < NLB; ++p) ldsm4(bh[p], pBh + p * (16 * PADB) + kb);
            #pragma unroll
            for (int mi = 0; mi < 4; ++mi)
                #pragma unroll
                for (int p = 0; p < NLB; ++p) {
                    mma16816(acc[mi][p * 2],     a[mi], bh[p][0], bh[p][1]);
                    mma16816(acc[mi][p * 2 + 1], a[mi], bh[p][2], bh[p][3]);
                }
            uint32_t bl[NLB][4];
            #pragma unroll
            for (int p = 0; p < NLB; ++p) ldsm4(bl[p], pBl + p * (16 * PADB) + kb);
            #pragma unroll
            for (int mi = 0; mi < 4; ++mi)
                #pragma unroll
                for (int p = 0; p < NLB; ++p) {
                    mma16816(acc[mi][p * 2],     a[mi], bl[p][0], bl[p][1]);
                    mma16816(acc[mi][p * 2 + 1], a[mi], bl[p][2], bl[p][3]);
                }
            #pragma unroll
            for (int mi = 0; mi < 4; ++mi) ldsm4(a[mi], pAl + mi * (16 * PADB) + kb);
            #pragma unroll
            for (int mi = 0; mi < 4; ++mi)
                #pragma unroll
                for (int p = 0; p < NLB; ++p) {
                    mma16816(acc[mi][p * 2],     a[mi], bh[p][0], bh[p][1]);
                    mma16816(acc[mi][p * 2 + 1], a[mi], bh[p][2], bh[p][3]);
                }
        }
    };

    issue(0, 0);
    issue(1, 1);
    #pragma unroll 1
    for (int t = 0; t < 4; ++t) {
        if (t < 3) asm volatile("cp.async.wait_group 1;" ::: "memory");
        else       asm volatile("cp.async.wait_group 0;" ::: "memory");
        __syncthreads();
        compute(t & 1);
        __syncthreads();
        if (t < 2) issue(t + 2, t & 1);
    }

    #pragma unroll
    for (int mi = 0; mi < 4; ++mi) {
        int r0 = m0 + wm * 64 + mi * 16 + (lane >> 2);
        #pragma unroll
        for (int nj = 0; nj < NFRAG; ++nj) {
            int c = wn * WARP_N + nj * 8 + (lane & 3) * 2;
            float bb0 = __ldg(&bias[c]);
            float bb1 = __ldg(&bias[c + 1]);
            const float* d = acc[mi][nj];
            float v00 = d[0] + bb0, v01 = d[1] + bb1;
            float v10 = d[2] + bb0, v11 = d[3] + bb1;
            if (RELU) {
                v00 = fmaxf(v00, 0.f); v01 = fmaxf(v01, 0.f);
                v10 = fmaxf(v10, 0.f); v11 = fmaxf(v11, 0.f);
            }
            if (r0 < NN) {
                if (SPLIT) {
                    __nv_bfloat162 H = __floats2bfloat162_rn(v00, v01);
                    __nv_bfloat162 L = __floats2bfloat162_rn(v00 - __bfloat162float(H.x),
                                                             v01 - __bfloat162float(H.y));
                    *(__nv_bfloat162*)(outHh + (size_t)r0 * DD + c) = H;
                    *(__nv_bfloat162*)(outHl + (size_t)r0 * DD + c) = L;
                    *(__half2*)(outH16 + (size_t)r0 * DD + c) = __floats2half2_rn(v00, v01);
                } else {
                    *(float2*)(outF + (size_t)r0 * BN + c) = make_float2(v00, v01);
                }
            }
            if (r0 + 8 < NN) {
                if (SPLIT) {
                    __nv_bfloat162 H = __floats2bfloat162_rn(v10, v11);
                    __nv_bfloat162 L = __floats2bfloat162_rn(v10 - __bfloat162float(H.x),
                                                             v11 - __bfloat162float(H.y));
                    *(__nv_bfloat162*)(outHh + (size_t)(r0 + 8) * DD + c) = H;
                    *(__nv_bfloat162*)(outHl + (size_t)(r0 + 8) * DD + c) = L;
                    *(__half2*)(outH16 + (size_t)(r0 + 8) * DD + c) = __floats2half2_rn(v10, v11);
                } else {
                    *(float2*)(outF + (size_t)(r0 + 8) * BN + c) = make_float2(v10, v11);
                }
            }
        }
    }
}

// ================= launch =================
extern "C" void kernel_launch(void* const* d_in, const int* in_sizes, int n_in,
                              void* d_out, int out_size) {
    (void)in_sizes; (void)n_in; (void)out_size;
    const float* x  = (const float*)d_in[0];
    const int*   ei = (const int*)d_in[1];
    const float* ew = (const float*)d_in[2];
    const float* W0 = (const float*)d_in[3];
    const float* b0 = (const float*)d_in[4];
    const float* W1 = (const float*)d_in[5];
    const float* b1 = (const float*)d_in[6];
    const float* W2 = (const float*)d_in[7];
    const float* b2 = (const float*)d_in[8];
    float* out = (float*)d_out;

    void *p_cnt, *p_xf16, *p_hf16;
    void *p_xhA, *p_xlA, *p_xhB, *p_xlB;
    void *p_wh0, *p_wl0, *p_wh1, *p_wl1, *p_wh2, *p_wl2;
    cudaGetSymbolAddress(&p_cnt,  g_cnt);
    cudaGetSymbolAddress(&p_xf16, g_xf16);
    cudaGetSymbolAddress(&p_hf16, g_hf16);
    cudaGetSymbolAddress(&p_xhA, g_xhA);
    cudaGetSymbolAddress(&p_xlA, g_xlA);
    cudaGetSymbolAddress(&p_xhB, g_xhB);
    cudaGetSymbolAddress(&p_xlB, g_xlB);
    cudaGetSymbolAddress(&p_wh0, g_Wh0);
    cudaGetSymbolAddress(&p_wl0, g_Wl0);
    cudaGetSymbolAddress(&p_wh1, g_Wh1);
    cudaGetSymbolAddress(&p_wl1, g_Wl1);
    cudaGetSymbolAddress(&p_wh2, g_Wh2);
    cudaGetSymbolAddress(&p_wl2, g_Wl2);

    const int SMEM128 = 2 * (2 * 128 * 144 + 2 * 128 * 144);
    const int SMEM64  = 2 * (2 * 128 * 144 + 2 * 64 * 144);
    cudaFuncSetAttribute(tgemm_kernel<128, true, true>,
                         cudaFuncAttributeMaxDynamicSharedMemorySize, SMEM128);
    cudaFuncSetAttribute(tgemm_kernel<64, false, false>,
                         cudaFuncAttributeMaxDynamicSharedMemorySize, SMEM64);

    cudaMemsetAsync(p_cnt, 0, NN * sizeof(int), 0);

    const int totW = 2 * 128 * KK + 64 * KK;
    prep_W<<<(totW + 255) / 256, 256>>>(W0, W1, W2);
    split_x<<<(NN * DD / 4 + 255) / 256, 256>>>(x);
    count_kernel<<<(NE / 4 + 255) / 256, 256>>>(ei);
    scan_p1<<<NBLK, 1024>>>();
    scan_p2<<<1, 64>>>();
    scan_p3<<<NBLK, 1024>>>();
    fill_kernel<<<(NE / 4 + 255) / 256, 256>>>(ei, ew);

    const int aggBlocks  = (NN + 7) / 8;
    const int gemmBlocks = (NN + 127) / 128;

    // layer 0
    agg_kernel<<<aggBlocks, 256>>>((const __half*)p_xf16);
    tgemm_kernel<128, true, true><<<gemmBlocks, 256, SMEM128>>>(
        (const __nv_bfloat16*)p_xhA, (const __nv_bfloat16*)p_xlA,
        (const __nv_bfloat16*)p_wh0, (const __nv_bfloat16*)p_wl0,
        b0, nullptr, (__nv_bfloat16*)p_xhB, (__nv_bfloat16*)p_xlB, (__half*)p_hf16);

    // layer 1
    agg_kernel<<<aggBlocks, 256>>>((const __half*)p_hf16);
    tgemm_kernel<128, true, true><<<gemmBlocks, 256, SMEM128>>>(
        (const __nv_bfloat16*)p_xhB, (const __nv_bfloat16*)p_xlB,
        (const __nv_bfloat16*)p_wh1, (const __nv_bfloat16*)p_wl1,
        b1, nullptr, (__nv_bfloat16*)p_xhA, (__nv_bfloat16*)p_xlA, (__half*)p_hf16);

    // layer 2
    agg_kernel<<<aggBlocks, 256>>>((const __half*)p_hf16);
    tgemm_kernel<64, false, false><<<gemmBlocks, 256, SMEM64>>>(
        (const __nv_bfloat16*)p_xhA, (const __nv_bfloat16*)p_xlA,
        (const __nv_bfloat16*)p_wh2, (const __nv_bfloat16*)p_wl2,
        b2, out, nullptr, nullptr, nullptr);
}

// round 9
// speedup vs baseline: 1.7835x; 1.0078x over previous
#include <cuda_runtime.h>
#include <cuda_bf16.h>
#include <cuda_fp16.h>
#include <cstdint>
#include <cstddef>

#define NN   50000
#define NE   800000
#define DD   128
#define KK   256
#define NBLK 49          // ceil(NN/1024)

// ================= low-level helpers =================
__device__ __forceinline__ uint32_t smem_u32(const void* p) {
    uint32_t a;
    asm("{ .reg .u64 t; cvta.to.shared.u64 t, %1; cvt.u32.u64 %0, t; }" : "=r"(a) : "l"(p));
    return a;
}
__device__ __forceinline__ void ldsm4(uint32_t* r, uint32_t addr) {
    asm volatile("ldmatrix.sync.aligned.m8n8.x4.shared.b16 {%0,%1,%2,%3}, [%4];"
                 : "=r"(r[0]), "=r"(r[1]), "=r"(r[2]), "=r"(r[3]) : "r"(addr));
}
__device__ __forceinline__ void mma16816(float* d, const uint32_t* a, uint32_t b0, uint32_t b1) {
    asm volatile(
        "mma.sync.aligned.m16n8k16.row.col.f32.bf16.bf16.f32 "
        "{%0,%1,%2,%3}, {%4,%5,%6,%7}, {%8,%9}, {%0,%1,%2,%3};"
        : "+f"(d[0]), "+f"(d[1]), "+f"(d[2]), "+f"(d[3])
        : "r"(a[0]), "r"(a[1]), "r"(a[2]), "r"(a[3]), "r"(b0), "r"(b1));
}
__device__ __forceinline__ void cpa16(uint32_t dst, const void* src, int sz) {
    asm volatile("cp.async.cg.shared.global [%0], [%1], 16, %2;"
                 :: "r"(dst), "l"(src), "r"(sz));
}
#define CPA_COMMIT() asm volatile("cp.async.commit_group;" ::: "memory")

// ================= device scratch =================
__device__ int   g_cnt[NN];
__device__ int   g_off[NN + 1];
__device__ int   g_bsum[NBLK];
__device__ int   g_bpre[NBLK];
__device__ int   g_col[NE];
__device__ float g_wgt[NE];
__device__ __half g_xf16[NN * DD];                   // fp16 x (agg gather, layer 0)
__device__ __half g_hf16[NN * DD];                   // fp16 hidden (agg gather, layers 1/2)
__device__ __nv_bfloat16 g_xhA[NN * DD], g_xlA[NN * DD];   // GEMM input split (ping)
__device__ __nv_bfloat16 g_xhB[NN * DD], g_xlB[NN * DD];   // (pong)
__device__ __nv_bfloat16 g_ah[NN * DD],  g_al[NN * DD];    // agg split
__device__ __nv_bfloat16 g_Wh0[128 * KK], g_Wl0[128 * KK];
__device__ __nv_bfloat16 g_Wh1[128 * KK], g_Wl1[128 * KK];
__device__ __nv_bfloat16 g_Wh2[64 * KK],  g_Wl2[64 * KK];

// ================= weight split (plain [n][k] layout) =================
__global__ void prep_W(const float* __restrict__ W0,
                       const float* __restrict__ W1,
                       const float* __restrict__ W2) {
    int i = blockIdx.x * 256 + threadIdx.x;
    const int L = 128 * KK;
    float w; __nv_bfloat16 *dh, *dl; int j;
    if (i < L)               { j = i;         w = W0[j]; dh = g_Wh0; dl = g_Wl0; }
    else if (i < 2 * L)      { j = i - L;     w = W1[j]; dh = g_Wh1; dl = g_Wl1; }
    else if (i < 2 * L + 64 * KK) { j = i - 2 * L; w = W2[j]; dh = g_Wh2; dl = g_Wl2; }
    else return;
    __nv_bfloat16 hi = __float2bfloat16(w);
    __nv_bfloat16 lo = __float2bfloat16(w - __bfloat162float(hi));
    dh[j] = hi;
    dl[j] = lo;
}

// ================= split x (once): bf16 hi/lo + fp16 shadow =================
__global__ void split_x(const float* __restrict__ x) {
    int i = blockIdx.x * 256 + threadIdx.x;         // float4 index
    if (i >= NN * DD / 4) return;
    float4 v = ((const float4*)x)[i];
    __nv_bfloat162 h0 = __floats2bfloat162_rn(v.x, v.y);
    __nv_bfloat162 h1 = __floats2bfloat162_rn(v.z, v.w);
    __nv_bfloat162 l0 = __floats2bfloat162_rn(v.x - __bfloat162float(h0.x),
                                              v.y - __bfloat162float(h0.y));
    __nv_bfloat162 l1 = __floats2bfloat162_rn(v.z - __bfloat162float(h1.x),
                                              v.w - __bfloat162float(h1.y));
    ((__nv_bfloat162*)g_xhA)[i * 2]     = h0;
    ((__nv_bfloat162*)g_xhA)[i * 2 + 1] = h1;
    ((__nv_bfloat162*)g_xlA)[i * 2]     = l0;
    ((__nv_bfloat162*)g_xlA)[i * 2 + 1] = l1;
    ((__half2*)g_xf16)[i * 2]     = __floats2half2_rn(v.x, v.y);
    ((__half2*)g_xf16)[i * 2 + 1] = __floats2half2_rn(v.z, v.w);
}

// ================= CSR build =================
__global__ void count_kernel(const int* __restrict__ ei) {
    int e4 = blockIdx.x * blockDim.x + threadIdx.x;   // 4 edges per thread
    if (e4 >= NE / 4) return;
    int4 r = ((const int4*)ei)[e4];
    atomicAdd(&g_cnt[r.x], 1);
    atomicAdd(&g_cnt[r.y], 1);
    atomicAdd(&g_cnt[r.z], 1);
    atomicAdd(&g_cnt[r.w], 1);
}

// -- 3-phase multi-block scan --
__global__ void scan_p1() {
    __shared__ int ws[32];
    int i = blockIdx.x * 1024 + threadIdx.x;
    int v = (i < NN) ? g_cnt[i] : 0;
    #pragma unroll
    for (int o = 16; o > 0; o >>= 1) v += __shfl_down_sync(0xffffffffu, v, o);
    if ((threadIdx.x & 31) == 0) ws[threadIdx.x >> 5] = v;
    __syncthreads();
    if (threadIdx.x < 32) {
        int t = ws[threadIdx.x];
        #pragma unroll
        for (int o = 16; o > 0; o >>= 1) t += __shfl_down_sync(0xffffffffu, t, o);
        if (threadIdx.x == 0) g_bsum[blockIdx.x] = t;
    }
}

__global__ void scan_p2() {
    int lane = threadIdx.x & 31;
    int wid  = threadIdx.x >> 5;
    __shared__ int wtot;
    int v = (threadIdx.x < NBLK) ? g_bsum[threadIdx.x] : 0;
    int incl = v;
    #pragma unroll
    for (int o = 1; o < 32; o <<= 1) {
        int t = __shfl_up_sync(0xffffffffu, incl, o);
        if (lane >= o) incl += t;
    }
    if (wid == 0 && lane == 31) wtot = incl;
    __syncthreads();
    int excl = incl - v + (wid ? wtot : 0);
    if (threadIdx.x < NBLK) g_bpre[threadIdx.x] = excl;
    if (threadIdx.x == 0) g_off[NN] = NE;
}

__global__ void scan_p3() {
    __shared__ int ws[32];
    const int tid = threadIdx.x, lane = tid & 31, wid = tid >> 5;
    int i = blockIdx.x * 1024 + tid;
    int v = (i < NN) ? g_cnt[i] : 0;
    int incl = v;
    #pragma unroll
    for (int o = 1; o < 32; o <<= 1) {
        int t = __shfl_up_sync(0xffffffffu, incl, o);
        if (lane >= o) incl += t;
    }
    if (lane == 31) ws[wid] = incl;
    __syncthreads();
    if (wid == 0) {
        int wv = (lane < 32) ? ws[lane] : 0;
        int s = wv;
        #pragma unroll
        for (int o = 1; o < 32; o <<= 1) {
            int t = __shfl_up_sync(0xffffffffu, s, o);
            if (lane >= o) s += t;
        }
        ws[lane] = s - wv;
    }
    __syncthreads();
    int o = g_bpre[blockIdx.x] + ws[wid] + incl - v;
    if (i < NN) { g_off[i] = o; g_cnt[i] = o; }
}

__global__ void fill_kernel(const int* __restrict__ ei, const float* __restrict__ ew) {
    int e4 = blockIdx.x * blockDim.x + threadIdx.x;
    if (e4 >= NE / 4) return;
    int4   r = ((const int4*)ei)[e4];
    int4   c = ((const int4*)(ei + NE))[e4];
    float4 w = ((const float4*)ew)[e4];
    int p;
    p = atomicAdd(&g_cnt[r.x], 1); g_col[p] = c.x; g_wgt[p] = w.x;
    p = atomicAdd(&g_cnt[r.y], 1); g_col[p] = c.y; g_wgt[p] = w.y;
    p = atomicAdd(&g_cnt[r.z], 1); g_col[p] = c.z; g_wgt[p] = w.z;
    p = atomicAdd(&g_cnt[r.w], 1); g_col[p] = c.w; g_wgt[p] = w.w;
}

// ======= aggregation: warp per node, fp16 gather, MLP=4 pipelined ============
__global__ void agg_kernel(const __half* __restrict__ xin) {
    int gw = (blockIdx.x * blockDim.x + threadIdx.x) >> 5;
    if (gw >= NN) return;
    const int lane = threadIdx.x & 31;
    const int s = g_off[gw];
    const int e = g_off[gw + 1];
    float4 acc = make_float4(0.f, 0.f, 0.f, 0.f);
    float wsum = 0.f;
    for (int base = s; base < e; base += 32) {
        int nn = min(32, e - base);
        int c = 0; float w = 0.f;
        if (lane < nn) { c = g_col[base + lane]; w = g_wgt[base + lane]; }
        wsum += w;
        int j = 0;
        for (; j + 4 <= nn; j += 4) {
            int cj0 = __shfl_sync(0xffffffffu, c, j);
            int cj1 = __shfl_sync(0xffffffffu, c, j + 1);
            int cj2 = __shfl_sync(0xffffffffu, c, j + 2);
            int cj3 = __shfl_sync(0xffffffffu, c, j + 3);
            float wj0 = __shfl_sync(0xffffffffu, w, j);
            float wj1 = __shfl_sync(0xffffffffu, w, j + 1);
            float wj2 = __shfl_sync(0xffffffffu, w, j + 2);
            float wj3 = __shfl_sync(0xffffffffu, w, j + 3);
            uint2 u0 = *(const uint2*)(xin + (size_t)cj0 * DD + lane * 4);
            uint2 u1 = *(const uint2*)(xin + (size_t)cj1 * DD + lane * 4);
            uint2 u2 = *(const uint2*)(xin + (size_t)cj2 * DD + lane * 4);
            uint2 u3 = *(const uint2*)(xin + (size_t)cj3 * DD + lane * 4);
            {
                float2 a = __half22float2(*(const __half2*)&u0.x);
                float2 b = __half22float2(*(const __half2*)&u0.y);
                acc.x = fmaf(a.x, wj0, acc.x); acc.y = fmaf(a.y, wj0, acc.y);
                acc.z = fmaf(b.x, wj0, acc.z); acc.w = fmaf(b.y, wj0, acc.w);
            }
            {
                float2 a = __half22float2(*(const __half2*)&u1.x);
                float2 b = __half22float2(*(const __half2*)&u1.y);
                acc.x = fmaf(a.x, wj1, acc.x); acc.y = fmaf(a.y, wj1, acc.y);
                acc.z = fmaf(b.x, wj1, acc.z); acc.w = fmaf(b.y, wj1, acc.w);
            }
            {
                float2 a = __half22float2(*(const __half2*)&u2.x);
                float2 b = __half22float2(*(const __half2*)&u2.y);
                acc.x = fmaf(a.x, wj2, acc.x); acc.y = fmaf(a.y, wj2, acc.y);
                acc.z = fmaf(b.x, wj2, acc.z); acc.w = fmaf(b.y, wj2, acc.w);
            }
            {
                float2 a = __half22float2(*(const __half2*)&u3.x);
                float2 b = __half22float2(*(const __half2*)&u3.y);
                acc.x = fmaf(a.x, wj3, acc.x); acc.y = fmaf(a.y, wj3, acc.y);
                acc.z = fmaf(b.x, wj3, acc.z); acc.w = fmaf(b.y, wj3, acc.w);
            }
        }
        for (; j < nn; ++j) {
            int cj = __shfl_sync(0xffffffffu, c, j);
            float wj = __shfl_sync(0xffffffffu, w, j);
            uint2 u = *(const uint2*)(xin + (size_t)cj * DD + lane * 4);
            float2 a = __half22float2(*(const __half2*)&u.x);
            float2 b = __half22float2(*(const __half2*)&u.y);
            acc.x = fmaf(a.x, wj, acc.x); acc.y = fmaf(a.y, wj, acc.y);
            acc.z = fmaf(b.x, wj, acc.z); acc.w = fmaf(b.y, wj, acc.w);
        }
    }
    #pragma unroll
    for (int o = 16; o > 0; o >>= 1) wsum += __shfl_xor_sync(0xffffffffu, wsum, o);
    float invd = 1.0f / fmaxf(wsum, 1.0f);
    float v0 = acc.x * invd, v1 = acc.y * invd, v2 = acc.z * invd, v3 = acc.w * invd;
    __nv_bfloat162 h01 = __floats2bfloat162_rn(v0, v1);
    __nv_bfloat162 h23 = __floats2bfloat162_rn(v2, v3);
    __nv_bfloat162 l01 = __floats2bfloat162_rn(v0 - __bfloat162float(h01.x),
                                               v1 - __bfloat162float(h01.y));
    __nv_bfloat162 l23 = __floats2bfloat162_rn(v2 - __bfloat162float(h23.x),
                                               v3 - __bfloat162float(h23.y));
    __nv_bfloat162* oh = (__nv_bfloat162*)g_ah + (size_t)gw * 64 + lane * 2;
    __nv_bfloat162* ol = (__nv_bfloat162*)g_al + (size_t)gw * 64 + lane * 2;
    oh[0] = h01; oh[1] = h23;
    ol[0] = l01; ol[1] = l23;
}

// ================= HMMA GEMM: out = [X|Agg] @ W^T + b =================
template <int BN, bool RELU, bool SPLIT>
__global__ void __launch_bounds__(256, 1) tgemm_kernel(
    const __nv_bfloat16* __restrict__ Xh, const __nv_bfloat16* __restrict__ Xl,
    const __nv_bfloat16* __restrict__ Wh, const __nv_bfloat16* __restrict__ Wl,
    const float* __restrict__ bias,
    float* __restrict__ outF,
    __nv_bfloat16* __restrict__ outHh, __nv_bfloat16* __restrict__ outHl,
    __half* __restrict__ outH16)
{
    extern __shared__ __align__(16) char smem[];
    constexpr int PADB  = 144;
    constexpr int ASZ   = 128 * PADB;
    constexpr int BSZ   = BN * PADB;
    constexpr int STAGE = 2 * ASZ + 2 * BSZ;
    constexpr int WARP_N = BN / 4;
    constexpr int NFRAG  = WARP_N / 8;
    constexpr int NLB    = NFRAG / 2;
    constexpr int BLOADS = (BN * 8) / 256;

    const int tid  = threadIdx.x;
    const int lane = tid & 31;
    const int wid  = tid >> 5;
    const int wm   = wid >> 2;
    const int wn   = wid & 3;
    const int m0   = blockIdx.x * 128;

    const uint32_t sbase = smem_u32(smem);
    const uint32_t offA = (uint32_t)((wm * 64 + (lane & 15)) * PADB + (lane >> 4) * 16);
    const uint32_t offB = (uint32_t)((wn * WARP_N + (lane & 7) + ((lane >> 4) << 3)) * PADB
                                     + (lane & 8) * 2);

    float acc[4][NFRAG][4];
    #pragma unroll
    for (int i = 0; i < 4; ++i)
        #pragma unroll
        for (int j = 0; j < NFRAG; ++j)
            #pragma unroll
            for (int q = 0; q < 4; ++q) acc[i][j][q] = 0.f;

    auto issue = [&](int t, int b) {
        const uint32_t st = sbase + b * STAGE;
        const __nv_bfloat16* axh = (t < 2) ? Xh : g_ah;
        const __nv_bfloat16* axl = (t < 2) ? Xl : g_al;
        const int colb = (t & 1) * 64;
        #pragma unroll
        for (int i = 0; i < 4; ++i) {
            int idx = tid + i * 256;
            int row = idx >> 3, ch = idx & 7;
            int gr = m0 + row;
            int ok = (gr < NN) ? 16 : 0;
            int grc = (gr < NN) ? gr : 0;
            size_t go = (size_t)grc * DD + colb + ch * 8;
            uint32_t sa = (uint32_t)(row * PADB + ch * 16);
            cpa16(st + sa,        axh + go, ok);
            cpa16(st + ASZ + sa,  axl + go, ok);
        }
        #pragma unroll
        for (int i = 0; i < BLOADS; ++i) {
            int idx = tid + i * 256;
            int row = idx >> 3, ch = idx & 7;
            size_t go = (size_t)row * KK + t * 64 + ch * 8;
            uint32_t sa = (uint32_t)(row * PADB + ch * 16);
            cpa16(st + 2 * ASZ + sa,       Wh + go, 16);
            cpa16(st + 2 * ASZ + BSZ + sa, Wl + go, 16);
        }
        CPA_COMMIT();
    };

    auto compute = [&](int b) {
        const uint32_t st  = sbase + b * STAGE;
        const uint32_t pAh = st + offA;
        const uint32_t pAl = st + ASZ + offA;
        const uint32_t pBh = st + 2 * ASZ + offB;
        const uint32_t pBl = st + 2 * ASZ + BSZ + offB;
        #pragma unroll
        for (int kk = 0; kk < 4; ++kk) {
            const int kb = kk * 32;
            uint32_t a[4][4];
            #pragma unroll
            for (int mi = 0; mi < 4; ++mi) ldsm4(a[mi], pAh + mi * (16 * PADB) + kb);
            uint32_t bh[NLB][4];
            #pragma unroll
            for (int p = 0; p < NLB; ++p) ldsm4(bh[p], pBh + p * (16 * PADB) + kb);
            #pragma unroll
            for (int mi = 0; mi < 4; ++mi)
                #pragma unroll
                for (int p = 0; p < NLB; ++p) {
                    mma16816(acc[mi][p * 2],     a[mi], bh[p][0], bh[p][1]);
                    mma16816(acc[mi][p * 2 + 1], a[mi], bh[p][2], bh[p][3]);
                }
            uint32_t bl[NLB][4];
            #pragma unroll
            for (int p = 0; p < NLB; ++p) ldsm4(bl[p], pBl + p * (16 * PADB) + kb);
            #pragma unroll
            for (int mi = 0; mi < 4; ++mi)
                #pragma unroll
                for (int p = 0; p < NLB; ++p) {
                    mma16816(acc[mi][p * 2],     a[mi], bl[p][0], bl[p][1]);
                    mma16816(acc[mi][p * 2 + 1], a[mi], bl[p][2], bl[p][3]);
                }
            #pragma unroll
            for (int mi = 0; mi < 4; ++mi) ldsm4(a[mi], pAl + mi * (16 * PADB) + kb);
            #pragma unroll
            for (int mi = 0; mi < 4; ++mi)
                #pragma unroll
                for (int p = 0; p < NLB; ++p) {
                    mma16816(acc[mi][p * 2],     a[mi], bh[p][0], bh[p][1]);
                    mma16816(acc[mi][p * 2 + 1], a[mi], bh[p][2], bh[p][3]);
                }
        }
    };

    issue(0, 0);
    issue(1, 1);
    #pragma unroll 1
    for (int t = 0; t < 4; ++t) {
        if (t < 3) asm volatile("cp.async.wait_group 1;" ::: "memory");
        else       asm volatile("cp.async.wait_group 0;" ::: "memory");
        __syncthreads();
        compute(t & 1);
        __syncthreads();
        if (t < 2) issue(t + 2, t & 1);
    }

    #pragma unroll
    for (int mi = 0; mi < 4; ++mi) {
        int r0 = m0 + wm * 64 + mi * 16 + (lane >> 2);
        #pragma unroll
        for (int nj = 0; nj < NFRAG; ++nj) {
            int c = wn * WARP_N + nj * 8 + (lane & 3) * 2;
            float bb0 = __ldg(&bias[c]);
            float bb1 = __ldg(&bias[c + 1]);
            const float* d = acc[mi][nj];
            float v00 = d[0] + bb0, v01 = d[1] + bb1;
            float v10 = d[2] + bb0, v11 = d[3] + bb1;
            if (RELU) {
                v00 = fmaxf(v00, 0.f); v01 = fmaxf(v01, 0.f);
                v10 = fmaxf(v10, 0.f); v11 = fmaxf(v11, 0.f);
            }
            if (r0 < NN) {
                if (SPLIT) {
                    __nv_bfloat162 H = __floats2bfloat162_rn(v00, v01);
                    __nv_bfloat162 L = __floats2bfloat162_rn(v00 - __bfloat162float(H.x),
                                                             v01 - __bfloat162float(H.y));
                    *(__nv_bfloat162*)(outHh + (size_t)r0 * DD + c) = H;
                    *(__nv_bfloat162*)(outHl + (size_t)r0 * DD + c) = L;
                    *(__half2*)(outH16 + (size_t)r0 * DD + c) = __floats2half2_rn(v00, v01);
                } else {
                    *(float2*)(outF + (size_t)r0 * BN + c) = make_float2(v00, v01);
                }
            }
            if (r0 + 8 < NN) {
                if (SPLIT) {
                    __nv_bfloat162 H = __floats2bfloat162_rn(v10, v11);
                    __nv_bfloat162 L = __floats2bfloat162_rn(v10 - __bfloat162float(H.x),
                                                             v11 - __bfloat162float(H.y));
                    *(__nv_bfloat162*)(outHh + (size_t)(r0 + 8) * DD + c) = H;
                    *(__nv_bfloat162*)(outHl + (size_t)(r0 + 8) * DD + c) = L;
                    *(__half2*)(outH16 + (size_t)(r0 + 8) * DD + c) = __floats2half2_rn(v10, v11);
                } else {
                    *(float2*)(outF + (size_t)(r0 + 8) * BN + c) = make_float2(v10, v11);
                }
            }
        }
    }
}

// ================= launch =================
extern "C" void kernel_launch(void* const* d_in, const int* in_sizes, int n_in,
                              void* d_out, int out_size) {
    (void)in_sizes; (void)n_in; (void)out_size;
    const float* x  = (const float*)d_in[0];
    const int*   ei = (const int*)d_in[1];
    const float* ew = (const float*)d_in[2];
    const float* W0 = (const float*)d_in[3];
    const float* b0 = (const float*)d_in[4];
    const float* W1 = (const float*)d_in[5];
    const float* b1 = (const float*)d_in[6];
    const float* W2 = (const float*)d_in[7];
    const float* b2 = (const float*)d_in[8];
    float* out = (float*)d_out;

    void *p_cnt, *p_xf16, *p_hf16;
    void *p_xhA, *p_xlA, *p_xhB, *p_xlB;
    void *p_wh0, *p_wl0, *p_wh1, *p_wl1, *p_wh2, *p_wl2;
    cudaGetSymbolAddress(&p_cnt,  g_cnt);
    cudaGetSymbolAddress(&p_xf16, g_xf16);
    cudaGetSymbolAddress(&p_hf16, g_hf16);
    cudaGetSymbolAddress(&p_xhA, g_xhA);
    cudaGetSymbolAddress(&p_xlA, g_xlA);
    cudaGetSymbolAddress(&p_xhB, g_xhB);
    cudaGetSymbolAddress(&p_xlB, g_xlB);
    cudaGetSymbolAddress(&p_wh0, g_Wh0);
    cudaGetSymbolAddress(&p_wl0, g_Wl0);
    cudaGetSymbolAddress(&p_wh1, g_Wh1);
    cudaGetSymbolAddress(&p_wl1, g_Wl1);
    cudaGetSymbolAddress(&p_wh2, g_Wh2);
    cudaGetSymbolAddress(&p_wl2, g_Wl2);

    const int SMEM128 = 2 * (2 * 128 * 144 + 2 * 128 * 144);
    const int SMEM64  = 2 * (2 * 128 * 144 + 2 * 64 * 144);
    cudaFuncSetAttribute(tgemm_kernel<128, true, true>,
                         cudaFuncAttributeMaxDynamicSharedMemorySize, SMEM128);
    cudaFuncSetAttribute(tgemm_kernel<64, false, false>,
                         cudaFuncAttributeMaxDynamicSharedMemorySize, SMEM64);

    // side stream + events (created once, outside capture; reused inside capture)
    static cudaStream_t s1 = nullptr;
    static cudaEvent_t ev_fork = nullptr, ev_join = nullptr;
    if (s1 == nullptr) {
        cudaStreamCreateWithFlags(&s1, cudaStreamNonBlocking);
        cudaEventCreateWithFlags(&ev_fork, cudaEventDisableTiming);
        cudaEventCreateWithFlags(&ev_join, cudaEventDisableTiming);
    }

    cudaMemsetAsync(p_cnt, 0, NN * sizeof(int), 0);

    // fork: CSR build chain on s1, feature prep on main stream
    cudaEventRecord(ev_fork, 0);
    cudaStreamWaitEvent(s1, ev_fork, 0);
    count_kernel<<<(NE / 4 + 255) / 256, 256, 0, s1>>>(ei);
    scan_p1<<<NBLK, 1024, 0, s1>>>();
    scan_p2<<<1, 64, 0, s1>>>();
    scan_p3<<<NBLK, 1024, 0, s1>>>();
    fill_kernel<<<(NE / 4 + 255) / 256, 256, 0, s1>>>(ei, ew);
    cudaEventRecord(ev_join, s1);

    const int totW = 2 * 128 * KK + 64 * KK;
    prep_W<<<(totW + 255) / 256, 256>>>(W0, W1, W2);
    split_x<<<(NN * DD / 4 + 255) / 256, 256>>>(x);

    cudaStreamWaitEvent(0, ev_join, 0);   // join before aggregation

    const int aggBlocks  = (NN + 7) / 8;
    const int gemmBlocks = (NN + 127) / 128;

    // layer 0
    agg_kernel<<<aggBlocks, 256>>>((const __half*)p_xf16);
    tgemm_kernel<128, true, true><<<gemmBlocks, 256, SMEM128>>>(
        (const __nv_bfloat16*)p_xhA, (const __nv_bfloat16*)p_xlA,
        (const __nv_bfloat16*)p_wh0, (const __nv_bfloat16*)p_wl0,
        b0, nullptr, (__nv_bfloat16*)p_xhB, (__nv_bfloat16*)p_xlB, (__half*)p_hf16);

    // layer 1
    agg_kernel<<<aggBlocks, 256>>>((const __half*)p_hf16);
    tgemm_kernel<128, true, true><<<gemmBlocks, 256, SMEM128>>>(
        (const __nv_bfloat16*)p_xhB, (const __nv_bfloat16*)p_xlB,
        (const __nv_bfloat16*)p_wh1, (const __nv_bfloat16*)p_wl1,
        b1, nullptr, (__nv_bfloat16*)p_xhA, (__nv_bfloat16*)p_xlA, (__half*)p_hf16);

    // layer 2
    agg_kernel<<<aggBlocks, 256>>>((const __half*)p_hf16);
    tgemm_kernel<64, false, false><<<gemmBlocks, 256, SMEM64>>>(
        (const __nv_bfloat16*)p_xhA, (const __nv_bfloat16*)p_xlA,
        (const __nv_bfloat16*)p_wh2, (const __nv_bfloat16*)p_wl2,
        b2, out, nullptr, nullptr, nullptr);
}

// round 10
// speedup vs baseline: 1.7860x; 1.0014x over previous
#include <cuda_runtime.h>
#include <cuda_bf16.h>
#include <cuda_fp16.h>
#include <cstdint>
#include <cstddef>

#define NN   50000
#define NE   800000
#define DD   128
#define KK   256
#define NBLK 49          // ceil(NN/1024)

// ================= low-level helpers =================
__device__ __forceinline__ uint32_t smem_u32(const void* p) {
    uint32_t a;
    asm("{ .reg .u64 t; cvta.to.shared.u64 t, %1; cvt.u32.u64 %0, t; }" : "=r"(a) : "l"(p));
    return a;
}
__device__ __forceinline__ void ldsm4(uint32_t* r, uint32_t addr) {
    asm volatile("ldmatrix.sync.aligned.m8n8.x4.shared.b16 {%0,%1,%2,%3}, [%4];"
                 : "=r"(r[0]), "=r"(r[1]), "=r"(r[2]), "=r"(r[3]) : "r"(addr));
}
__device__ __forceinline__ void mma16816(float* d, const uint32_t* a, uint32_t b0, uint32_t b1) {
    asm volatile(
        "mma.sync.aligned.m16n8k16.row.col.f32.bf16.bf16.f32 "
        "{%0,%1,%2,%3}, {%4,%5,%6,%7}, {%8,%9}, {%0,%1,%2,%3};"
        : "+f"(d[0]), "+f"(d[1]), "+f"(d[2]), "+f"(d[3])
        : "r"(a[0]), "r"(a[1]), "r"(a[2]), "r"(a[3]), "r"(b0), "r"(b1));
}
__device__ __forceinline__ void cpa16(uint32_t dst, const void* src, int sz) {
    asm volatile("cp.async.cg.shared.global [%0], [%1], 16, %2;"
                 :: "r"(dst), "l"(src), "r"(sz));
}
#define CPA_COMMIT() asm volatile("cp.async.commit_group;" ::: "memory")

// ================= device scratch =================
__device__ int   g_cnt[NN];
__device__ int   g_off[NN + 1];
__device__ int   g_bsum[NBLK];
__device__ int   g_bpre[NBLK];
__device__ int   g_col[NE];
__device__ float g_wgt[NE];
__device__ __half g_xf16[NN * DD];                   // fp16 x (agg gather, layer 0)
__device__ __half g_hf16[NN * DD];                   // fp16 hidden (agg gather, layers 1/2)
__device__ __nv_bfloat16 g_xhA[NN * DD], g_xlA[NN * DD];   // GEMM input split (ping)
__device__ __nv_bfloat16 g_xhB[NN * DD], g_xlB[NN * DD];   // (pong)
__device__ __nv_bfloat16 g_ah[NN * DD],  g_al[NN * DD];    // agg split
__device__ __nv_bfloat16 g_Wh0[128 * KK], g_Wl0[128 * KK];
__device__ __nv_bfloat16 g_Wh1[128 * KK], g_Wl1[128 * KK];
__device__ __nv_bfloat16 g_Wh2[64 * KK],  g_Wl2[64 * KK];

// ================= weight split (plain [n][k] layout) =================
__global__ void prep_W(const float* __restrict__ W0,
                       const float* __restrict__ W1,
                       const float* __restrict__ W2) {
    int i = blockIdx.x * 256 + threadIdx.x;
    const int L = 128 * KK;
    float w; __nv_bfloat16 *dh, *dl; int j;
    if (i < L)               { j = i;         w = W0[j]; dh = g_Wh0; dl = g_Wl0; }
    else if (i < 2 * L)      { j = i - L;     w = W1[j]; dh = g_Wh1; dl = g_Wl1; }
    else if (i < 2 * L + 64 * KK) { j = i - 2 * L; w = W2[j]; dh = g_Wh2; dl = g_Wl2; }
    else return;
    __nv_bfloat16 hi = __float2bfloat16(w);
    __nv_bfloat16 lo = __float2bfloat16(w - __bfloat162float(hi));
    dh[j] = hi;
    dl[j] = lo;
}

// ================= split x (once): bf16 hi/lo + fp16 shadow =================
__global__ void split_x(const float* __restrict__ x) {
    int i = blockIdx.x * 256 + threadIdx.x;         // float4 index
    if (i >= NN * DD / 4) return;
    float4 v = ((const float4*)x)[i];
    __nv_bfloat162 h0 = __floats2bfloat162_rn(v.x, v.y);
    __nv_bfloat162 h1 = __floats2bfloat162_rn(v.z, v.w);
    __nv_bfloat162 l0 = __floats2bfloat162_rn(v.x - __bfloat162float(h0.x),
                                              v.y - __bfloat162float(h0.y));
    __nv_bfloat162 l1 = __floats2bfloat162_rn(v.z - __bfloat162float(h1.x),
                                              v.w - __bfloat162float(h1.y));
    ((__nv_bfloat162*)g_xhA)[i * 2]     = h0;
    ((__nv_bfloat162*)g_xhA)[i * 2 + 1] = h1;
    ((__nv_bfloat162*)g_xlA)[i * 2]     = l0;
    ((__nv_bfloat162*)g_xlA)[i * 2 + 1] = l1;
    ((__half2*)g_xf16)[i * 2]     = __floats2half2_rn(v.x, v.y);
    ((__half2*)g_xf16)[i * 2 + 1] = __floats2half2_rn(v.z, v.w);
}

// ================= CSR build =================
__global__ void count_kernel(const int* __restrict__ ei) {
    int e4 = blockIdx.x * blockDim.x + threadIdx.x;   // 4 edges per thread
    if (e4 >= NE / 4) return;
    int4 r = ((const int4*)ei)[e4];
    atomicAdd(&g_cnt[r.x], 1);
    atomicAdd(&g_cnt[r.y], 1);
    atomicAdd(&g_cnt[r.z], 1);
    atomicAdd(&g_cnt[r.w], 1);
}

// -- 3-phase multi-block scan --
__global__ void scan_p1() {
    __shared__ int ws[32];
    int i = blockIdx.x * 1024 + threadIdx.x;
    int v = (i < NN) ? g_cnt[i] : 0;
    #pragma unroll
    for (int o = 16; o > 0; o >>= 1) v += __shfl_down_sync(0xffffffffu, v, o);
    if ((threadIdx.x & 31) == 0) ws[threadIdx.x >> 5] = v;
    __syncthreads();
    if (threadIdx.x < 32) {
        int t = ws[threadIdx.x];
        #pragma unroll
        for (int o = 16; o > 0; o >>= 1) t += __shfl_down_sync(0xffffffffu, t, o);
        if (threadIdx.x == 0) g_bsum[blockIdx.x] = t;
    }
}

__global__ void scan_p2() {
    int lane = threadIdx.x & 31;
    int wid  = threadIdx.x >> 5;
    __shared__ int wtot;
    int v = (threadIdx.x < NBLK) ? g_bsum[threadIdx.x] : 0;
    int incl = v;
    #pragma unroll
    for (int o = 1; o < 32; o <<= 1) {
        int t = __shfl_up_sync(0xffffffffu, incl, o);
        if (lane >= o) incl += t;
    }
    if (wid == 0 && lane == 31) wtot = incl;
    __syncthreads();
    int excl = incl - v + (wid ? wtot : 0);
    if (threadIdx.x < NBLK) g_bpre[threadIdx.x] = excl;
    if (threadIdx.x == 0) g_off[NN] = NE;
}

__global__ void scan_p3() {
    __shared__ int ws[32];
    const int tid = threadIdx.x, lane = tid & 31, wid = tid >> 5;
    int i = blockIdx.x * 1024 + tid;
    int v = (i < NN) ? g_cnt[i] : 0;
    int incl = v;
    #pragma unroll
    for (int o = 1; o < 32; o <<= 1) {
        int t = __shfl_up_sync(0xffffffffu, incl, o);
        if (lane >= o) incl += t;
    }
    if (lane == 31) ws[wid] = incl;
    __syncthreads();
    if (wid == 0) {
        int wv = (lane < 32) ? ws[lane] : 0;
        int s = wv;
        #pragma unroll
        for (int o = 1; o < 32; o <<= 1) {
            int t = __shfl_up_sync(0xffffffffu, s, o);
            if (lane >= o) s += t;
        }
        ws[lane] = s - wv;
    }
    __syncthreads();
    int o = g_bpre[blockIdx.x] + ws[wid] + incl - v;
    if (i < NN) { g_off[i] = o; g_cnt[i] = o; }
}

__global__ void fill_kernel(const int* __restrict__ ei, const float* __restrict__ ew) {
    int e4 = blockIdx.x * blockDim.x + threadIdx.x;
    if (e4 >= NE / 4) return;
    int4   r = ((const int4*)ei)[e4];
    int4   c = ((const int4*)(ei + NE))[e4];
    float4 w = ((const float4*)ew)[e4];
    int p;
    p = atomicAdd(&g_cnt[r.x], 1); g_col[p] = c.x; g_wgt[p] = w.x;
    p = atomicAdd(&g_cnt[r.y], 1); g_col[p] = c.y; g_wgt[p] = w.y;
    p = atomicAdd(&g_cnt[r.z], 1); g_col[p] = c.z; g_wgt[p] = w.z;
    p = atomicAdd(&g_cnt[r.w], 1); g_col[p] = c.w; g_wgt[p] = w.w;
}

// ======= aggregation: warp per node, fp16 gather, MLP=4 pipelined ============
__global__ void agg_kernel(const __half* __restrict__ xin) {
    int gw = (blockIdx.x * blockDim.x + threadIdx.x) >> 5;
    if (gw >= NN) return;
    const int lane = threadIdx.x & 31;
    const int s = g_off[gw];
    const int e = g_off[gw + 1];
    float4 acc = make_float4(0.f, 0.f, 0.f, 0.f);
    float wsum = 0.f;
    for (int base = s; base < e; base += 32) {
        int nn = min(32, e - base);
        int c = 0; float w = 0.f;
        if (lane < nn) { c = g_col[base + lane]; w = g_wgt[base + lane]; }
        wsum += w;
        int j = 0;
        for (; j + 4 <= nn; j += 4) {
            int cj0 = __shfl_sync(0xffffffffu, c, j);
            int cj1 = __shfl_sync(0xffffffffu, c, j + 1);
            int cj2 = __shfl_sync(0xffffffffu, c, j + 2);
            int cj3 = __shfl_sync(0xffffffffu, c, j + 3);
            float wj0 = __shfl_sync(0xffffffffu, w, j);
            float wj1 = __shfl_sync(0xffffffffu, w, j + 1);
            float wj2 = __shfl_sync(0xffffffffu, w, j + 2);
            float wj3 = __shfl_sync(0xffffffffu, w, j + 3);
            uint2 u0 = *(const uint2*)(xin + (size_t)cj0 * DD + lane * 4);
            uint2 u1 = *(const uint2*)(xin + (size_t)cj1 * DD + lane * 4);
            uint2 u2 = *(const uint2*)(xin + (size_t)cj2 * DD + lane * 4);
            uint2 u3 = *(const uint2*)(xin + (size_t)cj3 * DD + lane * 4);
            {
                float2 a = __half22float2(*(const __half2*)&u0.x);
                float2 b = __half22float2(*(const __half2*)&u0.y);
                acc.x = fmaf(a.x, wj0, acc.x); acc.y = fmaf(a.y, wj0, acc.y);
                acc.z = fmaf(b.x, wj0, acc.z); acc.w = fmaf(b.y, wj0, acc.w);
            }
            {
                float2 a = __half22float2(*(const __half2*)&u1.x);
                float2 b = __half22float2(*(const __half2*)&u1.y);
                acc.x = fmaf(a.x, wj1, acc.x); acc.y = fmaf(a.y, wj1, acc.y);
                acc.z = fmaf(b.x, wj1, acc.z); acc.w = fmaf(b.y, wj1, acc.w);
            }
            {
                float2 a = __half22float2(*(const __half2*)&u2.x);
                float2 b = __half22float2(*(const __half2*)&u2.y);
                acc.x = fmaf(a.x, wj2, acc.x); acc.y = fmaf(a.y, wj2, acc.y);
                acc.z = fmaf(b.x, wj2, acc.z); acc.w = fmaf(b.y, wj2, acc.w);
            }
            {
                float2 a = __half22float2(*(const __half2*)&u3.x);
                float2 b = __half22float2(*(const __half2*)&u3.y);
                acc.x = fmaf(a.x, wj3, acc.x); acc.y = fmaf(a.y, wj3, acc.y);
                acc.z = fmaf(b.x, wj3, acc.z); acc.w = fmaf(b.y, wj3, acc.w);
            }
        }
        for (; j < nn; ++j) {
            int cj = __shfl_sync(0xffffffffu, c, j);
            float wj = __shfl_sync(0xffffffffu, w, j);
            uint2 u = *(const uint2*)(xin + (size_t)cj * DD + lane * 4);
            float2 a = __half22float2(*(const __half2*)&u.x);
            float2 b = __half22float2(*(const __half2*)&u.y);
            acc.x = fmaf(a.x, wj, acc.x); acc.y = fmaf(a.y, wj, acc.y);
            acc.z = fmaf(b.x, wj, acc.z); acc.w = fmaf(b.y, wj, acc.w);
        }
    }
    #pragma unroll
    for (int o = 16; o > 0; o >>= 1) wsum += __shfl_xor_sync(0xffffffffu, wsum, o);
    float invd = 1.0f / fmaxf(wsum, 1.0f);
    float v0 = acc.x * invd, v1 = acc.y * invd, v2 = acc.z * invd, v3 = acc.w * invd;
    __nv_bfloat162 h01 = __floats2bfloat162_rn(v0, v1);
    __nv_bfloat162 h23 = __floats2bfloat162_rn(v2, v3);
    __nv_bfloat162 l01 = __floats2bfloat162_rn(v0 - __bfloat162float(h01.x),
                                               v1 - __bfloat162float(h01.y));
    __nv_bfloat162 l23 = __floats2bfloat162_rn(v2 - __bfloat162float(h23.x),
                                               v3 - __bfloat162float(h23.y));
    __nv_bfloat162* oh = (__nv_bfloat162*)g_ah + (size_t)gw * 64 + lane * 2;
    __nv_bfloat162* ol = (__nv_bfloat162*)g_al + (size_t)gw * 64 + lane * 2;
    oh[0] = h01; oh[1] = h23;
    ol[0] = l01; ol[1] = l23;
}

// ================= HMMA GEMM: out = [X|Agg] @ W^T + b =================
// BK=32, 8 K-tiles, double-buffered; stage = 40KB (BN=128) -> 2 CTAs/SM.
template <int BN, bool RELU, bool SPLIT>
__global__ void __launch_bounds__(256, 2) tgemm_kernel(
    const __nv_bfloat16* __restrict__ Xh, const __nv_bfloat16* __restrict__ Xl,
    const __nv_bfloat16* __restrict__ Wh, const __nv_bfloat16* __restrict__ Wl,
    const float* __restrict__ bias,
    float* __restrict__ outF,
    __nv_bfloat16* __restrict__ outHh, __nv_bfloat16* __restrict__ outHl,
    __half* __restrict__ outH16)
{
    extern __shared__ __align__(16) char smem[];
    constexpr int PADB  = 80;                  // 32 bf16 = 64B row + 16B pad
    constexpr int ASZ   = 128 * PADB;          // 10240
    constexpr int BSZ   = BN * PADB;
    constexpr int STAGE = 2 * ASZ + 2 * BSZ;
    constexpr int WARP_N = BN / 4;
    constexpr int NFRAG  = WARP_N / 8;
    constexpr int NLB    = NFRAG / 2;
    constexpr int BLOADS = (BN * 4) / 256;     // B 16B-chunks per thread (2 or 1)

    const int tid  = threadIdx.x;
    const int lane = tid & 31;
    const int wid  = tid >> 5;
    const int wm   = wid >> 2;
    const int wn   = wid & 3;
    const int m0   = blockIdx.x * 128;

    const uint32_t sbase = smem_u32(smem);
    const uint32_t offA = (uint32_t)((wm * 64 + (lane & 15)) * PADB + (lane >> 4) * 16);
    const uint32_t offB = (uint32_t)((wn * WARP_N + (lane & 7) + ((lane >> 4) << 3)) * PADB
                                     + (lane & 8) * 2);

    float acc[4][NFRAG][4];
    #pragma unroll
    for (int i = 0; i < 4; ++i)
        #pragma unroll
        for (int j = 0; j < NFRAG; ++j)
            #pragma unroll
            for (int q = 0; q < 4; ++q) acc[i][j][q] = 0.f;

    // tile t covers global k [t*32, t*32+32): t<4 from X, t>=4 from Agg
    auto issue = [&](int t, int b) {
        const uint32_t st = sbase + b * STAGE;
        const __nv_bfloat16* axh = (t < 4) ? Xh : g_ah;
        const __nv_bfloat16* axl = (t < 4) ? Xl : g_al;
        const int colb = (t & 3) * 32;
        #pragma unroll
        for (int i = 0; i < 2; ++i) {
            int idx = tid + i * 256;            // 0..511: 128 rows x 4 chunks
            int row = idx >> 2, ch = idx & 3;
            int gr = m0 + row;
            int ok = (gr < NN) ? 16 : 0;
            int grc = (gr < NN) ? gr : 0;
            size_t go = (size_t)grc * DD + colb + ch * 8;
            uint32_t sa = (uint32_t)(row * PADB + ch * 16);
            cpa16(st + sa,        axh + go, ok);
            cpa16(st + ASZ + sa,  axl + go, ok);
        }
        #pragma unroll
        for (int i = 0; i < BLOADS; ++i) {
            int idx = tid + i * 256;            // BN rows x 4 chunks
            int row = idx >> 2, ch = idx & 3;
            size_t go = (size_t)row * KK + t * 32 + ch * 8;
            uint32_t sa = (uint32_t)(row * PADB + ch * 16);
            cpa16(st + 2 * ASZ + sa,       Wh + go, 16);
            cpa16(st + 2 * ASZ + BSZ + sa, Wl + go, 16);
        }
        CPA_COMMIT();
    };

    auto compute = [&](int b) {
        const uint32_t st  = sbase + b * STAGE;
        const uint32_t pAh = st + offA;
        const uint32_t pAl = st + ASZ + offA;
        const uint32_t pBh = st + 2 * ASZ + offB;
        const uint32_t pBl = st + 2 * ASZ + BSZ + offB;
        #pragma unroll
        for (int kk = 0; kk < 2; ++kk) {
            const int kb = kk * 32;             // 16 bf16 = 32 bytes per step
            uint32_t a[4][4];
            #pragma unroll
            for (int mi = 0; mi < 4; ++mi) ldsm4(a[mi], pAh + mi * (16 * PADB) + kb);
            uint32_t bh[NLB][4];
            #pragma unroll
            for (int p = 0; p < NLB; ++p) ldsm4(bh[p], pBh + p * (16 * PADB) + kb);
            #pragma unroll
            for (int mi = 0; mi < 4; ++mi)
                #pragma unroll
                for (int p = 0; p < NLB; ++p) {
                    mma16816(acc[mi][p * 2],     a[mi], bh[p][0], bh[p][1]);
                    mma16816(acc[mi][p * 2 + 1], a[mi], bh[p][2], bh[p][3]);
                }
            uint32_t bl[NLB][4];
            #pragma unroll
            for (int p = 0; p < NLB; ++p) ldsm4(bl[p], pBl + p * (16 * PADB) + kb);
            #pragma unroll
            for (int mi = 0; mi < 4; ++mi)
                #pragma unroll
                for (int p = 0; p < NLB; ++p) {
                    mma16816(acc[mi][p * 2],     a[mi], bl[p][0], bl[p][1]);
                    mma16816(acc[mi][p * 2 + 1], a[mi], bl[p][2], bl[p][3]);
                }
            #pragma unroll
            for (int mi = 0; mi < 4; ++mi) ldsm4(a[mi], pAl + mi * (16 * PADB) + kb);
            #pragma unroll
            for (int mi = 0; mi < 4; ++mi)
                #pragma unroll
                for (int p = 0; p < NLB; ++p) {
                    mma16816(acc[mi][p * 2],     a[mi], bh[p][0], bh[p][1]);
                    mma16816(acc[mi][p * 2 + 1], a[mi], bh[p][2], bh[p][3]);
                }
        }
    };

    issue(0, 0);
    issue(1, 1);
    #pragma unroll 1
    for (int t = 0; t < 8; ++t) {
        if (t < 7) asm volatile("cp.async.wait_group 1;" ::: "memory");
        else       asm volatile("cp.async.wait_group 0;" ::: "memory");
        __syncthreads();
        compute(t & 1);
        __syncthreads();
        if (t < 6) issue(t + 2, t & 1);
    }

    #pragma unroll
    for (int mi = 0; mi < 4; ++mi) {
        int r0 = m0 + wm * 64 + mi * 16 + (lane >> 2);
        #pragma unroll
        for (int nj = 0; nj < NFRAG; ++nj) {
            int c = wn * WARP_N + nj * 8 + (lane & 3) * 2;
            float bb0 = __ldg(&bias[c]);
            float bb1 = __ldg(&bias[c + 1]);
            const float* d = acc[mi][nj];
            float v00 = d[0] + bb0, v01 = d[1] + bb1;
            float v10 = d[2] + bb0, v11 = d[3] + bb1;
            if (RELU) {
                v00 = fmaxf(v00, 0.f); v01 = fmaxf(v01, 0.f);
                v10 = fmaxf(v10, 0.f); v11 = fmaxf(v11, 0.f);
            }
            if (r0 < NN) {
                if (SPLIT) {
                    __nv_bfloat162 H = __floats2bfloat162_rn(v00, v01);
                    __nv_bfloat162 L = __floats2bfloat162_rn(v00 - __bfloat162float(H.x),
                                                             v01 - __bfloat162float(H.y));
                    *(__nv_bfloat162*)(outHh + (size_t)r0 * DD + c) = H;
                    *(__nv_bfloat162*)(outHl + (size_t)r0 * DD + c) = L;
                    *(__half2*)(outH16 + (size_t)r0 * DD + c) = __floats2half2_rn(v00, v01);
                } else {
                    *(float2*)(outF + (size_t)r0 * BN + c) = make_float2(v00, v01);
                }
            }
            if (r0 + 8 < NN) {
                if (SPLIT) {
                    __nv_bfloat162 H = __floats2bfloat162_rn(v10, v11);
                    __nv_bfloat162 L = __floats2bfloat162_rn(v10 - __bfloat162float(H.x),
                                                             v11 - __bfloat162float(H.y));
                    *(__nv_bfloat162*)(outHh + (size_t)(r0 + 8) * DD + c) = H;
                    *(__nv_bfloat162*)(outHl + (size_t)(r0 + 8) * DD + c) = L;
                    *(__half2*)(outH16 + (size_t)(r0 + 8) * DD + c) = __floats2half2_rn(v10, v11);
                } else {
                    *(float2*)(outF + (size_t)(r0 + 8) * BN + c) = make_float2(v10, v11);
                }
            }
        }
    }
}

// ================= launch =================
extern "C" void kernel_launch(void* const* d_in, const int* in_sizes, int n_in,
                              void* d_out, int out_size) {
    (void)in_sizes; (void)n_in; (void)out_size;
    const float* x  = (const float*)d_in[0];
    const int*   ei = (const int*)d_in[1];
    const float* ew = (const float*)d_in[2];
    const float* W0 = (const float*)d_in[3];
    const float* b0 = (const float*)d_in[4];
    const float* W1 = (const float*)d_in[5];
    const float* b1 = (const float*)d_in[6];
    const float* W2 = (const float*)d_in[7];
    const float* b2 = (const float*)d_in[8];
    float* out = (float*)d_out;

    void *p_cnt, *p_xf16, *p_hf16;
    void *p_xhA, *p_xlA, *p_xhB, *p_xlB;
    void *p_wh0, *p_wl0, *p_wh1, *p_wl1, *p_wh2, *p_wl2;
    cudaGetSymbolAddress(&p_cnt,  g_cnt);
    cudaGetSymbolAddress(&p_xf16, g_xf16);
    cudaGetSymbolAddress(&p_hf16, g_hf16);
    cudaGetSymbolAddress(&p_xhA, g_xhA);
    cudaGetSymbolAddress(&p_xlA, g_xlA);
    cudaGetSymbolAddress(&p_xhB, g_xhB);
    cudaGetSymbolAddress(&p_xlB, g_xlB);
    cudaGetSymbolAddress(&p_wh0, g_Wh0);
    cudaGetSymbolAddress(&p_wl0, g_Wl0);
    cudaGetSymbolAddress(&p_wh1, g_Wh1);
    cudaGetSymbolAddress(&p_wl1, g_Wl1);
    cudaGetSymbolAddress(&p_wh2, g_Wh2);
    cudaGetSymbolAddress(&p_wl2, g_Wl2);

    const int SMEM128 = 2 * (2 * 128 * 80 + 2 * 128 * 80);   // 81920
    const int SMEM64  = 2 * (2 * 128 * 80 + 2 * 64 * 80);    // 61440
    cudaFuncSetAttribute(tgemm_kernel<128, true, true>,
                         cudaFuncAttributeMaxDynamicSharedMemorySize, SMEM128);
    cudaFuncSetAttribute(tgemm_kernel<64, false, false>,
                         cudaFuncAttributeMaxDynamicSharedMemorySize, SMEM64);

    // side stream + events (created once, outside capture; reused inside capture)
    static cudaStream_t s1 = nullptr;
    static cudaEvent_t ev_fork = nullptr, ev_join = nullptr;
    if (s1 == nullptr) {
        cudaStreamCreateWithFlags(&s1, cudaStreamNonBlocking);
        cudaEventCreateWithFlags(&ev_fork, cudaEventDisableTiming);
        cudaEventCreateWithFlags(&ev_join, cudaEventDisableTiming);
    }

    cudaMemsetAsync(p_cnt, 0, NN * sizeof(int), 0);

    // fork: CSR build chain on s1, feature prep on main stream
    cudaEventRecord(ev_fork, 0);
    cudaStreamWaitEvent(s1, ev_fork, 0);
    count_kernel<<<(NE / 4 + 255) / 256, 256, 0, s1>>>(ei);
    scan_p1<<<NBLK, 1024, 0, s1>>>();
    scan_p2<<<1, 64, 0, s1>>>();
    scan_p3<<<NBLK, 1024, 0, s1>>>();
    fill_kernel<<<(NE / 4 + 255) / 256, 256, 0, s1>>>(ei, ew);
    cudaEventRecord(ev_join, s1);

    const int totW = 2 * 128 * KK + 64 * KK;
    prep_W<<<(totW + 255) / 256, 256>>>(W0, W1, W2);
    split_x<<<(NN * DD / 4 + 255) / 256, 256>>>(x);

    cudaStreamWaitEvent(0, ev_join, 0);   // join before aggregation

    const int aggBlocks  = (NN + 7) / 8;
    const int gemmBlocks = (NN + 127) / 128;

    // layer 0
    agg_kernel<<<aggBlocks, 256>>>((const __half*)p_xf16);
    tgemm_kernel<128, true, true><<<gemmBlocks, 256, SMEM128>>>(
        (const __nv_bfloat16*)p_xhA, (const __nv_bfloat16*)p_xlA,
        (const __nv_bfloat16*)p_wh0, (const __nv_bfloat16*)p_wl0,
        b0, nullptr, (__nv_bfloat16*)p_xhB, (__nv_bfloat16*)p_xlB, (__half*)p_hf16);

    // layer 1
    agg_kernel<<<aggBlocks, 256>>>((const __half*)p_hf16);
    tgemm_kernel<128, true, true><<<gemmBlocks, 256, SMEM128>>>(
        (const __nv_bfloat16*)p_xhB, (const __nv_bfloat16*)p_xlB,
        (const __nv_bfloat16*)p_wh1, (const __nv_bfloat16*)p_wl1,
        b1, nullptr, (__nv_bfloat16*)p_xhA, (__nv_bfloat16*)p_xlA, (__half*)p_hf16);

    // layer 2
    agg_kernel<<<aggBlocks, 256>>>((const __half*)p_hf16);
    tgemm_kernel<64, false, false><<<gemmBlocks, 256, SMEM64>>>(
        (const __nv_bfloat16*)p_xhA, (const __nv_bfloat16*)p_xlA,
        (const __nv_bfloat16*)p_wh2, (const __nv_bfloat16*)p_wl2,
        b2, out, nullptr, nullptr, nullptr);
}